// round 2
// baseline (speedup 1.0000x reference)
#include <cuda_runtime.h>
#include <math.h>

// Problem constants
#define B_    4
#define N_    2000
#define K_    30
#define H_    128
#define HEADS_ 4
#define D_    32
#define NIN_  256
#define NODES (B_ * N_)

// Shared memory layout (floats)
//  s_hv   [128]
//  s_hupd [128]
//  s_xKE  [30*128]
//  s_xKV  [30*128]
//  s_xEV  [30*256]
//  s_vs   [30*128]
//  s_logit[4*32]
//  s_att  [4*32]
//  s_mask [32]
#define SMEM_FLOATS (128 + 128 + 3840 + 3840 + 7680 + 3840 + 128 + 128 + 32)
#define SMEM_BYTES  (SMEM_FLOATS * 4)

__global__ __launch_bounds__(256, 2)
void neighbor_attn_kernel(const float* __restrict__ h_V,
                          const float* __restrict__ h_EV,
                          const float* __restrict__ h_KV,
                          const float* __restrict__ h_KE,
                          const float* __restrict__ maskg,
                          const float* __restrict__ W_Q,
                          const float* __restrict__ W_K1,
                          const float* __restrict__ W_K2,
                          const float* __restrict__ W_V,
                          const float* __restrict__ W_O,
                          float* __restrict__ out)
{
    extern __shared__ float sm[];
    float* s_hv    = sm;                 // 128
    float* s_hupd  = s_hv   + 128;       // 128
    float* s_xKE   = s_hupd + 128;       // 3840
    float* s_xKV   = s_xKE  + 3840;      // 3840
    float* s_xEV   = s_xKV  + 3840;      // 7680
    float* s_vs    = s_xEV  + 7680;      // 3840
    float* s_logit = s_vs   + 3840;      // 128
    float* s_att   = s_logit + 128;      // 128
    float* s_mask  = s_att  + 128;       // 32

    const int node = blockIdx.x;
    const int tid  = threadIdx.x;

    // ---------------- cooperative loads (contiguous, float4) ----------------
    {
        const float4* gKE = (const float4*)(h_KE + (size_t)node * 3840);
        const float4* gKV = (const float4*)(h_KV + (size_t)node * 3840);
        const float4* gEV = (const float4*)(h_EV + (size_t)node * 7680);
        float4* dKE = (float4*)s_xKE;
        float4* dKV = (float4*)s_xKV;
        float4* dEV = (float4*)s_xEV;
        #pragma unroll
        for (int i = tid; i < 960; i += 256) { dKE[i] = gKE[i]; dKV[i] = gKV[i]; }
        for (int i = tid; i < 1920; i += 256) { dEV[i] = gEV[i]; }
        if (tid < 32) ((float4*)s_hv)[tid] = ((const float4*)(h_V + (size_t)node * 128))[tid];
        if (tid < K_) s_mask[tid] = maskg[(size_t)node * K_ + tid];
    }
    __syncthreads();

    const int j = tid & 127;

    if (tid < 128) {
        // ============ Group A: Q, K1, K2 projections + trilinear logits ============
        // Q[j] = dot(W_Q[j,:], h_V_row)
        float q = 0.f;
        {
            const float4* wq = (const float4*)(W_Q + (size_t)j * H_);
            const float4* hv = (const float4*)s_hv;
            #pragma unroll
            for (int d = 0; d < 32; d++) {
                float4 w = wq[d], x = hv[d];
                q += w.x * x.x + w.y * x.y + w.z * x.z + w.w * x.w;
            }
        }

        float k1a[K_], k2a[K_];
        #pragma unroll
        for (int k = 0; k < K_; k++) { k1a[k] = 0.f; k2a[k] = 0.f; }

        const float4* w1p = (const float4*)(W_K1 + (size_t)j * H_);
        const float4* w2p = (const float4*)(W_K2 + (size_t)j * H_);
        for (int d4 = 0; d4 < 32; d4++) {
            const float4 w1 = w1p[d4];
            const float4 w2 = w2p[d4];
            const float* xa0 = s_xKE + d4 * 4;
            const float* xb0 = s_xKV + d4 * 4;
            #pragma unroll
            for (int k = 0; k < K_; k++) {
                float4 xa = *(const float4*)(xa0 + k * 128);
                float4 xb = *(const float4*)(xb0 + k * 128);
                k1a[k] += w1.x * xa.x + w1.y * xa.y + w1.z * xa.z + w1.w * xa.w;
                k2a[k] += w2.x * xb.x + w2.y * xb.y + w2.z * xb.z + w2.w * xb.w;
            }
        }

        // logits[h][k] = (1/D) * sum_{d in head} Q*K1*K2 ; warp w == head w
        const int head = j >> 5;
        #pragma unroll
        for (int k = 0; k < K_; k++) {
            float p = q * k1a[k] * k2a[k];
            p += __shfl_xor_sync(0xffffffffu, p, 16);
            p += __shfl_xor_sync(0xffffffffu, p, 8);
            p += __shfl_xor_sync(0xffffffffu, p, 4);
            p += __shfl_xor_sync(0xffffffffu, p, 2);
            p += __shfl_xor_sync(0xffffffffu, p, 1);
            if ((j & 31) == 0) s_logit[head * 32 + k] = p * (1.0f / 32.0f);
        }
    } else {
        // ============ Group B: V projection ============
        float va[K_];
        #pragma unroll
        for (int k = 0; k < K_; k++) va[k] = 0.f;

        const float4* wv = (const float4*)(W_V + (size_t)j * NIN_);
        for (int d4 = 0; d4 < 64; d4++) {
            const float4 w = wv[d4];
            const float* xe0 = s_xEV + d4 * 4;
            #pragma unroll
            for (int k = 0; k < K_; k++) {
                float4 x = *(const float4*)(xe0 + k * 256);
                va[k] += w.x * x.x + w.y * x.y + w.z * x.z + w.w * x.w;
            }
        }
        #pragma unroll
        for (int k = 0; k < K_; k++) s_vs[k * 128 + j] = va[k];
    }
    __syncthreads();

    // ---------------- masked softmax over K per head (warp h handles head h) ----------------
    if (tid < 128) {
        const int h = tid >> 5, lane = tid & 31;
        const float NEG = -3.4028234663852886e38f;  // float32.min, matches reference
        float mk = 0.f;
        float l = NEG;
        if (lane < K_) {
            mk = s_mask[lane];
            float lg = s_logit[h * 32 + lane];
            l = (mk > 0.f) ? lg : NEG;
        }
        float m = l;
        m = fmaxf(m, __shfl_xor_sync(0xffffffffu, m, 16));
        m = fmaxf(m, __shfl_xor_sync(0xffffffffu, m, 8));
        m = fmaxf(m, __shfl_xor_sync(0xffffffffu, m, 4));
        m = fmaxf(m, __shfl_xor_sync(0xffffffffu, m, 2));
        m = fmaxf(m, __shfl_xor_sync(0xffffffffu, m, 1));
        float p = (lane < K_) ? expf(l - m) : 0.f;
        float s = p;
        s += __shfl_xor_sync(0xffffffffu, s, 16);
        s += __shfl_xor_sync(0xffffffffu, s, 8);
        s += __shfl_xor_sync(0xffffffffu, s, 4);
        s += __shfl_xor_sync(0xffffffffu, s, 2);
        s += __shfl_xor_sync(0xffffffffu, s, 1);
        if (lane < K_) s_att[h * 32 + lane] = (p / s) * mk;
    }
    __syncthreads();

    // ---------------- aggregation: h_upd[j] = sum_k attend[h(j)][k] * V[k][j] ----------------
    if (tid < 128) {
        const int h = tid >> 5;
        float acc = 0.f;
        #pragma unroll
        for (int k = 0; k < K_; k++)
            acc += s_att[h * 32 + k] * s_vs[k * 128 + tid];
        s_hupd[tid] = acc;
    }
    __syncthreads();

    // ---------------- output projection: out[i] = dot(W_O[i,:], h_upd) ----------------
    if (tid < 128) {
        const float4* wo = (const float4*)(W_O + (size_t)tid * H_);
        const float4* hu = (const float4*)s_hupd;
        float acc = 0.f;
        #pragma unroll
        for (int c = 0; c < 32; c++) {
            float4 w = wo[c], x = hu[c];
            acc += w.x * x.x + w.y * x.y + w.z * x.z + w.w * x.w;
        }
        out[(size_t)node * H_ + tid] = acc;
    }
}

extern "C" void kernel_launch(void* const* d_in, const int* in_sizes, int n_in,
                              void* d_out, int out_size)
{
    const float* h_V  = (const float*)d_in[0];
    const float* h_EV = (const float*)d_in[1];
    const float* h_KV = (const float*)d_in[2];
    const float* h_KE = (const float*)d_in[3];
    const float* mask = (const float*)d_in[4];
    const float* W_Q  = (const float*)d_in[5];
    const float* W_K1 = (const float*)d_in[6];
    const float* W_K2 = (const float*)d_in[7];
    const float* W_V  = (const float*)d_in[8];
    const float* W_O  = (const float*)d_in[9];
    float* out = (float*)d_out;

    cudaFuncSetAttribute(neighbor_attn_kernel,
                         cudaFuncAttributeMaxDynamicSharedMemorySize, SMEM_BYTES);
    neighbor_attn_kernel<<<NODES, 256, SMEM_BYTES>>>(
        h_V, h_EV, h_KV, h_KE, mask, W_Q, W_K1, W_K2, W_V, W_O, out);
}

// round 5
// speedup vs baseline: 1.7704x; 1.7704x over previous
#include <cuda_runtime.h>
#include <cuda_bf16.h>
#include <cstdint>
#include <math.h>

// ---------------- problem constants ----------------
#define B_     4
#define N_     2000
#define K_     30
#define H_     128
#define NIN_   256
#define NODES  (B_ * N_)
#define G_     4              // nodes per CTA
#define MROWS  (G_ * K_)      // 120 valid rows of the 128-row M tile
#define GRID   (NODES / G_)   // 2000 CTAs

// ---------------- smem layout (bytes) ----------------
#define OFF_AHI   0          // A tile hi [128 rows x 256B (128 bf16)] swizzled
#define OFF_ALO   32768
#define OFF_BHI   65536      // B (weights) tile hi
#define OFF_BLO   98304
#define OFF_RED   131072     // K1 store / V reduction buffer: 128 x 132 f32 = 67584
#define OFF_HV    198656     // 4x128 f32
#define OFF_Q     200704     // 4x128 f32
#define OFF_LOGIT 202752     // 120x4 f32 (1920)
#define OFF_ATT   204672     // 16x30 f32 (1920)
#define OFF_MASK  206592     // 120 f32 (512 pad)
#define OFF_HUPD  207104     // 4x128 f32
#define SMEM_BYTES 209152

// pre-split, pre-swizzled weight images: [K1hi,K1lo,K2hi,K2lo,V0hi,V0lo,V1hi,V1lo]
__device__ uint4 g_wimg[8][2048];   // 8 x 32KB

// ---------------- helpers ----------------
static __device__ __forceinline__ uint32_t smem_u32(const void* p) {
    uint32_t a;
    asm("{ .reg .u64 t; cvta.to.shared.u64 t, %1; cvt.u32.u64 %0, t; }" : "=r"(a) : "l"(p));
    return a;
}
static __device__ __forceinline__ uint32_t pack2bf16(float a, float b) {
    __nv_bfloat162 t = __floats2bfloat162_rn(a, b);
    return *reinterpret_cast<uint32_t*>(&t);
}
// row-major [row][128 bf16], 256B rows, XOR swizzle of 16B chunk with (row&7)
static __device__ __forceinline__ uint32_t sw_off(int row, int col /*bf16 idx*/) {
    int chunk = col >> 3;
    return (uint32_t)(row * 256 + (((chunk ^ (row & 7)) << 4)) + ((col & 7) << 1));
}
static __device__ __forceinline__ void ldsm4(uint32_t* r, uint32_t addr) {
    asm volatile("ldmatrix.sync.aligned.m8n8.x4.shared.b16 {%0,%1,%2,%3}, [%4];"
                 : "=r"(r[0]), "=r"(r[1]), "=r"(r[2]), "=r"(r[3]) : "r"(addr));
}
static __device__ __forceinline__ void mma16816(float* c, const uint32_t* a, uint32_t b0, uint32_t b1) {
    asm volatile("mma.sync.aligned.m16n8k16.row.col.f32.bf16.bf16.f32 "
                 "{%0,%1,%2,%3}, {%4,%5,%6,%7}, {%8,%9}, {%0,%1,%2,%3};"
                 : "+f"(c[0]), "+f"(c[1]), "+f"(c[2]), "+f"(c[3])
                 : "r"(a[0]), "r"(a[1]), "r"(a[2]), "r"(a[3]), "r"(b0), "r"(b1));
}

// ---------------- weight pre-split kernel ----------------
__global__ void convert_weights_kernel(const float* __restrict__ Wk1,
                                       const float* __restrict__ Wk2,
                                       const float* __restrict__ Wv)
{
    int idx = blockIdx.x * blockDim.x + threadIdx.x;   // 4 * 16384
    int img = idx >> 14;
    int e = idx & 16383;
    int row = e >> 7, col = e & 127;
    float v;
    if (img == 0)      v = Wk1[row * 128 + col];
    else if (img == 1) v = Wk2[row * 128 + col];
    else if (img == 2) v = Wv[row * 256 + col];
    else               v = Wv[row * 256 + 128 + col];
    __nv_bfloat16 hi = __float2bfloat16(v);
    __nv_bfloat16 lo = __float2bfloat16(v - __bfloat162float(hi));
    uint32_t off = sw_off(row, col);
    *reinterpret_cast<__nv_bfloat16*>((char*)g_wimg[img * 2]     + off) = hi;
    *reinterpret_cast<__nv_bfloat16*>((char*)g_wimg[img * 2 + 1] + off) = lo;
}

// ---------------- main fused kernel ----------------
__global__ __launch_bounds__(256, 1)
void neighbor_attn_hmma_kernel(const float* __restrict__ h_V,
                               const float* __restrict__ h_EV,
                               const float* __restrict__ h_KV,
                               const float* __restrict__ h_KE,
                               const float* __restrict__ maskg,
                               const float* __restrict__ W_Q,
                               const float* __restrict__ W_O,
                               float* __restrict__ out)
{
    extern __shared__ char sm[];
    const uint32_t sb = smem_u32(sm);
    const int tid = threadIdx.x;
    const int wid = tid >> 5;
    const int lane = tid & 31;
    const int node0 = blockIdx.x * G_;

    float* s_red   = (float*)(sm + OFF_RED);     // also K1 store
    float* s_hv    = (float*)(sm + OFF_HV);
    float* s_q     = (float*)(sm + OFF_Q);
    float* s_logit = (float*)(sm + OFF_LOGIT);
    float* s_att   = (float*)(sm + OFF_ATT);
    float* s_mask  = (float*)(sm + OFF_MASK);
    float* s_hupd  = (float*)(sm + OFF_HUPD);

    // ---- load h_V rows & mask ----
    if (tid < 128) ((float4*)s_hv)[tid] = ((const float4*)(h_V + (size_t)node0 * 128))[tid];
    if (tid < MROWS) s_mask[tid] = maskg[(size_t)node0 * K_ + tid];
    __syncthreads();

    // ---- Q projection (SIMT) ----
    #pragma unroll
    for (int rep = 0; rep < 2; rep++) {
        int o = tid + rep * 256;
        int g = o >> 7, j = o & 127;
        const float4* wq = (const float4*)(W_Q + (size_t)j * 128);
        const float4* hv = (const float4*)(s_hv + g * 128);
        float acc = 0.f;
        #pragma unroll
        for (int d = 0; d < 32; d++) {
            float4 w = wq[d], x = hv[d];
            acc += w.x * x.x + w.y * x.y + w.z * x.z + w.w * x.w;
        }
        s_q[o] = acc;
    }

    // fragment row/col ids
    const int qrow = lane >> 2;            // 0..7
    const int dn   = (lane & 3) * 2;       // 0,2,4,6
    const int rA   = wid * 16 + qrow;
    const int rB   = rA + 8;
    const int gA = (rA < MROWS) ? (rA / K_) : 3;
    const int kA = rA % K_;
    const int gB = (rB < MROWS) ? (rB / K_) : 3;
    const int kB = rB % K_;

    // ldmatrix lane geometry
    const int li  = lane & 7;
    const int grp = lane >> 3;
    const int arow   = wid * 16 + li + ((grp & 1) << 3);
    const int acsel  = grp >> 1;           // +0/+1 k-chunk
    const uint32_t aoffb = (uint32_t)(arow * 256);
    const int amask = arow & 7;

    float acc[16][4];

    // phase tables: A src, row stride, col offset, weight image pair
    const float* asrc[4] = { h_KE + (size_t)node0 * 3840, h_KV + (size_t)node0 * 3840,
                             h_EV + (size_t)node0 * 7680, h_EV + (size_t)node0 * 7680 };
    const int    arst[4] = { 128, 128, 256, 256 };
    const int    acol[4] = { 0, 0, 0, 128 };

    for (int ph = 0; ph < 4; ph++) {
        // ---- stage A: LDG f32 -> bf16 hi/lo -> swizzled STS ----
        {
            const float* src = asrc[ph];
            const int rs = arst[ph], co = acol[ph];
            for (int s = tid; s < 4096; s += 256) {
                int r = s >> 5;
                int c4 = s & 31;
                int col = c4 << 2;
                float4 v = make_float4(0.f, 0.f, 0.f, 0.f);
                if (r < MROWS) v = *(const float4*)(src + (size_t)r * rs + co + col);
                float hx = __bfloat162float(__float2bfloat16(v.x));
                float hy = __bfloat162float(__float2bfloat16(v.y));
                float hz = __bfloat162float(__float2bfloat16(v.z));
                float hw = __bfloat162float(__float2bfloat16(v.w));
                uint2 hv2 = make_uint2(pack2bf16(hx, hy), pack2bf16(hz, hw));
                uint2 lv2 = make_uint2(pack2bf16(v.x - hx, v.y - hy), pack2bf16(v.z - hz, v.w - hw));
                uint32_t off = sw_off(r, col);
                *(uint2*)(sm + OFF_AHI + off) = hv2;
                *(uint2*)(sm + OFF_ALO + off) = lv2;
            }
        }
        // ---- stage B: copy pre-swizzled weight images ----
        {
            const uint4* wh = g_wimg[ph * 2];
            const uint4* wl = g_wimg[ph * 2 + 1];
            for (int i = tid; i < 2048; i += 256) {
                *(uint4*)(sm + OFF_BHI + i * 16) = wh[i];
                *(uint4*)(sm + OFF_BLO + i * 16) = wl[i];
            }
        }
        __syncthreads();

        if (ph != 3) {
            #pragma unroll
            for (int t = 0; t < 16; t++)
                #pragma unroll
                for (int j = 0; j < 4; j++) acc[t][j] = 0.f;
        }

        // ---- k-loop: 8 k16 steps ----
        #pragma unroll
        for (int ks = 0; ks < 8; ks++) {
            uint32_t ahi[4], alo[4];
            uint32_t achunk = (uint32_t)(((2 * ks + acsel) ^ amask) << 4);
            ldsm4(ahi, sb + OFF_AHI + aoffb + achunk);
            ldsm4(alo, sb + OFF_ALO + aoffb + achunk);
            #pragma unroll
            for (int tp = 0; tp < 8; tp++) {
                int t0 = 2 * tp, t1 = 2 * tp + 1;
                int brow = (tp << 4) + ((grp >> 1) << 3) + li;
                uint32_t bo = (uint32_t)(brow * 256 + (((2 * ks + (grp & 1)) ^ (brow & 7)) << 4));
                uint32_t bhi[4], blo[4];
                ldsm4(bhi, sb + OFF_BHI + bo);
                ldsm4(blo, sb + OFF_BLO + bo);
                mma16816(acc[t0], ahi, bhi[0], bhi[1]);
                mma16816(acc[t1], ahi, bhi[2], bhi[3]);
                mma16816(acc[t0], ahi, blo[0], blo[1]);
                mma16816(acc[t1], ahi, blo[2], blo[3]);
                mma16816(acc[t0], alo, bhi[0], bhi[1]);
                mma16816(acc[t1], alo, bhi[2], bhi[3]);
            }
        }
        __syncthreads();   // staging buffers free for next phase

        if (ph == 0) {
            // ---- store K1 to smem ----
            #pragma unroll
            for (int t = 0; t < 16; t++) {
                int n0 = t * 8 + dn;
                *(float2*)&s_red[rA * 132 + n0] = make_float2(acc[t][0], acc[t][1]);
                *(float2*)&s_red[rB * 132 + n0] = make_float2(acc[t][2], acc[t][3]);
            }
            // no extra sync needed: rows are warp-private, next read is after later syncs
        } else if (ph == 1) {
            // ---- trilinear logits from K2 acc + K1(smem) + Q(smem) ----
            float part[8];
            #pragma unroll
            for (int i = 0; i < 8; i++) part[i] = 0.f;
            #pragma unroll
            for (int t = 0; t < 16; t++) {
                int h = t >> 2;
                int n0 = t * 8 + dn;
                float2 k1A = *(float2*)&s_red[rA * 132 + n0];
                float2 k1B = *(float2*)&s_red[rB * 132 + n0];
                float2 qA  = *(float2*)&s_q[gA * 128 + n0];
                float2 qB  = *(float2*)&s_q[gB * 128 + n0];
                part[h]     += qA.x * k1A.x * acc[t][0] + qA.y * k1A.y * acc[t][1];
                part[4 + h] += qB.x * k1B.x * acc[t][2] + qB.y * k1B.y * acc[t][3];
            }
            #pragma unroll
            for (int i = 0; i < 8; i++) {
                part[i] += __shfl_xor_sync(0xffffffffu, part[i], 1);
                part[i] += __shfl_xor_sync(0xffffffffu, part[i], 2);
            }
            if ((lane & 3) == 0) {
                #pragma unroll
                for (int h = 0; h < 4; h++) {
                    if (rA < MROWS) s_logit[rA * 4 + h] = part[h] * (1.0f / 32.0f);
                    if (rB < MROWS) s_logit[rB * 4 + h] = part[4 + h] * (1.0f / 32.0f);
                }
            }
            __syncthreads();
            // ---- masked softmax per (g,h), serial over 30 neighbors ----
            if (tid < 16) {
                const int g = tid >> 2, h = tid & 3;
                const float NEG = -3.4028234663852886e38f;  // float32.min, matches reference
                float m = NEG;
                for (int k = 0; k < K_; k++) {
                    float msk = s_mask[g * K_ + k];
                    float l = (msk > 0.f) ? s_logit[(g * K_ + k) * 4 + h] : NEG;
                    m = fmaxf(m, l);
                }
                float ssum = 0.f;
                for (int k = 0; k < K_; k++) {
                    float msk = s_mask[g * K_ + k];
                    float l = (msk > 0.f) ? s_logit[(g * K_ + k) * 4 + h] : NEG;
                    float e = expf(l - m);
                    s_att[(g * 4 + h) * K_ + k] = e;
                    ssum += e;
                }
                float inv = 1.0f / ssum;
                for (int k = 0; k < K_; k++)
                    s_att[(g * 4 + h) * K_ + k] *= inv * s_mask[g * K_ + k];
            }
            // s_att consumed only after phase-3 sync; staging syncs provide ordering
        }
    }

    // ---- scale V acc by attend, store to reduction buffer ----
    {
        float aAh[4], aBh[4];
        #pragma unroll
        for (int h = 0; h < 4; h++) {
            aAh[h] = (rA < MROWS) ? s_att[(gA * 4 + h) * K_ + kA] : 0.f;
            aBh[h] = (rB < MROWS) ? s_att[(gB * 4 + h) * K_ + kB] : 0.f;
        }
        #pragma unroll
        for (int t = 0; t < 16; t++) {
            int h = t >> 2;
            int n0 = t * 8 + dn;
            *(float2*)&s_red[rA * 132 + n0] = make_float2(aAh[h] * acc[t][0], aAh[h] * acc[t][1]);
            *(float2*)&s_red[rB * 132 + n0] = make_float2(aBh[h] * acc[t][2], aBh[h] * acc[t][3]);
        }
    }
    __syncthreads();

    // ---- reduce over neighbors ----
    #pragma unroll
    for (int rep = 0; rep < 2; rep++) {
        int o = tid + rep * 256;
        int g = o >> 7, j = o & 127;
        float acc2 = 0.f;
        #pragma unroll
        for (int k = 0; k < K_; k++)
            acc2 += s_red[(g * K_ + k) * 132 + j];
        s_hupd[o] = acc2;
    }
    __syncthreads();

    // ---- output projection ----
    #pragma unroll
    for (int rep = 0; rep < 2; rep++) {
        int o = tid + rep * 256;
        int g = o >> 7, i = o & 127;
        const float4* wo = (const float4*)(W_O + (size_t)i * 128);
        const float4* hu = (const float4*)(s_hupd + g * 128);
        float acc2 = 0.f;
        #pragma unroll
        for (int c = 0; c < 32; c++) {
            float4 w = wo[c], x = hu[c];
            acc2 += w.x * x.x + w.y * x.y + w.z * x.z + w.w * x.w;
        }
        out[(size_t)(node0 + g) * 128 + i] = acc2;
    }
}

extern "C" void kernel_launch(void* const* d_in, const int* in_sizes, int n_in,
                              void* d_out, int out_size)
{
    const float* h_V  = (const float*)d_in[0];
    const float* h_EV = (const float*)d_in[1];
    const float* h_KV = (const float*)d_in[2];
    const float* h_KE = (const float*)d_in[3];
    const float* mask = (const float*)d_in[4];
    const float* W_Q  = (const float*)d_in[5];
    const float* W_K1 = (const float*)d_in[6];
    const float* W_K2 = (const float*)d_in[7];
    const float* W_V  = (const float*)d_in[8];
    const float* W_O  = (const float*)d_in[9];
    float* out = (float*)d_out;

    convert_weights_kernel<<<256, 256>>>(W_K1, W_K2, W_V);

    cudaFuncSetAttribute(neighbor_attn_hmma_kernel,
                         cudaFuncAttributeMaxDynamicSharedMemorySize, SMEM_BYTES);
    neighbor_attn_hmma_kernel<<<GRID, 256, SMEM_BYTES>>>(
        h_V, h_EV, h_KV, h_KE, mask, W_Q, W_O, out);
}

// round 6
// speedup vs baseline: 1.9090x; 1.0783x over previous
#include <cuda_runtime.h>
#include <cuda_bf16.h>
#include <cuda_fp16.h>
#include <cstdint>
#include <math.h>

// ---------------- problem constants ----------------
#define B_     4
#define N_     2000
#define K_     30
#define H_     128
#define NIN_   256
#define NODES  (B_ * N_)
#define G_     4              // nodes per CTA
#define MROWS  (G_ * K_)      // 120 valid rows of the 128-row M tile
#define GRID   (NODES / G_)   // 2000 CTAs

// ---------------- smem layout (bytes) ----------------
// staging (per k-half, 64 cols): A hi/lo 16KB each, B hi/lo 16KB each
#define OFF_AHI   0
#define OFF_ALO   16384
#define OFF_BHI   32768
#define OFF_BLO   49152
#define OFF_K1    65536      // K1 fp16: 120 x 132 half (31680 -> pad 31744)
#define OFF_HV    97280      // 4x128 f32
#define OFF_Q     99328      // 4x128 f32
#define OFF_LOGIT 101376     // 120x4 f32
#define OFF_ATT   103424     // 16x30 f32
#define OFF_MASK  105472     // 120 f32
#define OFF_HUPD  105984     // 4x128 f32
#define SMEM_BYTES 108032
// V-reduction buffer (120 x 132 f32 = 63360) aliases the staging area [0, 65536)
#define OFF_RED   0

// pre-split, pre-swizzled weight images, per phase / split / k-half:
// index = ph*4 + sp*2 + half   (ph: 0=K1,1=K2,2=V0,3=V1; sp: 0=hi,1=lo)
__device__ uint4 g_wimg[16][1024];   // 16 x 16KB

// ---------------- helpers ----------------
static __device__ __forceinline__ uint32_t smem_u32(const void* p) {
    uint32_t a;
    asm("{ .reg .u64 t; cvta.to.shared.u64 t, %1; cvt.u32.u64 %0, t; }" : "=r"(a) : "l"(p));
    return a;
}
static __device__ __forceinline__ uint32_t pack2bf16(float a, float b) {
    __nv_bfloat162 t = __floats2bfloat162_rn(a, b);
    return *reinterpret_cast<uint32_t*>(&t);
}
// row-major [row][64 bf16] = 128B rows; XOR-swizzle 16B chunk with (row&7)
static __device__ __forceinline__ uint32_t sw64(int row, int col /*bf16 idx 0..63*/) {
    return (uint32_t)(row * 128 + (((col >> 3) ^ (row & 7)) << 4) + ((col & 7) << 1));
}
static __device__ __forceinline__ void ldsm4(uint32_t* r, uint32_t addr) {
    asm volatile("ldmatrix.sync.aligned.m8n8.x4.shared.b16 {%0,%1,%2,%3}, [%4];"
                 : "=r"(r[0]), "=r"(r[1]), "=r"(r[2]), "=r"(r[3]) : "r"(addr));
}
static __device__ __forceinline__ void mma16816(float* c, const uint32_t* a, uint32_t b0, uint32_t b1) {
    asm volatile("mma.sync.aligned.m16n8k16.row.col.f32.bf16.bf16.f32 "
                 "{%0,%1,%2,%3}, {%4,%5,%6,%7}, {%8,%9}, {%0,%1,%2,%3};"
                 : "+f"(c[0]), "+f"(c[1]), "+f"(c[2]), "+f"(c[3])
                 : "r"(a[0]), "r"(a[1]), "r"(a[2]), "r"(a[3]), "r"(b0), "r"(b1));
}

// ---------------- weight pre-split kernel ----------------
__global__ void convert_weights_kernel(const float* __restrict__ Wk1,
                                       const float* __restrict__ Wk2,
                                       const float* __restrict__ Wv)
{
    int idx = blockIdx.x * blockDim.x + threadIdx.x;   // 4 * 16384
    int img = idx >> 14;                               // phase base 0..3
    int e = idx & 16383;
    int row = e >> 7, col = e & 127;
    float v;
    if (img == 0)      v = Wk1[row * 128 + col];
    else if (img == 1) v = Wk2[row * 128 + col];
    else if (img == 2) v = Wv[row * 256 + col];
    else               v = Wv[row * 256 + 128 + col];
    __nv_bfloat16 hi = __float2bfloat16(v);
    __nv_bfloat16 lo = __float2bfloat16(v - __bfloat162float(hi));
    int half = col >> 6, lcol = col & 63;
    uint32_t off = sw64(row, lcol);
    *reinterpret_cast<__nv_bfloat16*>((char*)g_wimg[img * 4 + half]     + off) = hi;
    *reinterpret_cast<__nv_bfloat16*>((char*)g_wimg[img * 4 + 2 + half] + off) = lo;
}

// ---------------- main fused kernel ----------------
__global__ __launch_bounds__(256, 2)
void neighbor_attn_hmma_kernel(const float* __restrict__ h_V,
                               const float* __restrict__ h_EV,
                               const float* __restrict__ h_KV,
                               const float* __restrict__ h_KE,
                               const float* __restrict__ maskg,
                               const float* __restrict__ W_Q,
                               const float* __restrict__ W_O,
                               float* __restrict__ out)
{
    extern __shared__ char sm[];
    const uint32_t sb = smem_u32(sm);
    const int tid = threadIdx.x;
    const int wid = tid >> 5;
    const int lane = tid & 31;
    const int node0 = blockIdx.x * G_;

    float*  s_red   = (float*)(sm + OFF_RED);    // aliases staging; used post-MMA only
    __half* s_k1    = (__half*)(sm + OFF_K1);
    float*  s_hv    = (float*)(sm + OFF_HV);
    float*  s_q     = (float*)(sm + OFF_Q);
    float*  s_logit = (float*)(sm + OFF_LOGIT);
    float*  s_att   = (float*)(sm + OFF_ATT);
    float*  s_mask  = (float*)(sm + OFF_MASK);
    float*  s_hupd  = (float*)(sm + OFF_HUPD);

    // ---- load h_V rows & mask ----
    if (tid < 128) ((float4*)s_hv)[tid] = ((const float4*)(h_V + (size_t)node0 * 128))[tid];
    if (tid < MROWS) s_mask[tid] = maskg[(size_t)node0 * K_ + tid];
    __syncthreads();

    // ---- Q projection (SIMT) ----
    #pragma unroll
    for (int rep = 0; rep < 2; rep++) {
        int o = tid + rep * 256;
        int g = o >> 7, j = o & 127;
        const float4* wq = (const float4*)(W_Q + (size_t)j * 128);
        const float4* hv = (const float4*)(s_hv + g * 128);
        float acc0 = 0.f;
        #pragma unroll
        for (int d = 0; d < 32; d++) {
            float4 w = wq[d], x = hv[d];
            acc0 += w.x * x.x + w.y * x.y + w.z * x.z + w.w * x.w;
        }
        s_q[o] = acc0;
    }

    // fragment row/col ids
    const int qrow = lane >> 2;            // 0..7
    const int dn   = (lane & 3) * 2;       // 0,2,4,6
    const int rA   = wid * 16 + qrow;
    const int rB   = rA + 8;
    const int gA = (rA < MROWS) ? (rA / K_) : 3;
    const int kA = rA % K_;
    const int gB = (rB < MROWS) ? (rB / K_) : 3;
    const int kB = rB % K_;

    // ldmatrix lane geometry
    const int li  = lane & 7;
    const int grp = lane >> 3;
    const int arow  = wid * 16 + li + ((grp & 1) << 3);
    const int acsel = grp >> 1;            // k-chunk +0/+1
    const uint32_t aoffb = (uint32_t)(arow * 128);
    const int amask = arow & 7;

    float acc[16][4];

    const float* asrc[4] = { h_KE + (size_t)node0 * 3840, h_KV + (size_t)node0 * 3840,
                             h_EV + (size_t)node0 * 7680, h_EV + (size_t)node0 * 7680 };
    const int    arst[4] = { 128, 128, 256, 256 };
    const int    acol[4] = { 0, 0, 0, 128 };

    for (int ph = 0; ph < 4; ph++) {
        for (int half = 0; half < 2; half++) {
            // ---- stage A half: LDG f32 -> bf16 hi/lo -> swizzled STS ----
            {
                const float* src = asrc[ph];
                const int rs = arst[ph], co = acol[ph] + half * 64;
                #pragma unroll
                for (int s = tid; s < 2048; s += 256) {
                    int r = s >> 4;
                    int col = (s & 15) << 2;
                    float4 v = make_float4(0.f, 0.f, 0.f, 0.f);
                    if (r < MROWS) v = *(const float4*)(src + (size_t)r * rs + co + col);
                    float hx = __bfloat162float(__float2bfloat16(v.x));
                    float hy = __bfloat162float(__float2bfloat16(v.y));
                    float hz = __bfloat162float(__float2bfloat16(v.z));
                    float hw = __bfloat162float(__float2bfloat16(v.w));
                    uint2 hv2 = make_uint2(pack2bf16(hx, hy), pack2bf16(hz, hw));
                    uint2 lv2 = make_uint2(pack2bf16(v.x - hx, v.y - hy), pack2bf16(v.z - hz, v.w - hw));
                    uint32_t off = sw64(r, col);
                    *(uint2*)(sm + OFF_AHI + off) = hv2;
                    *(uint2*)(sm + OFF_ALO + off) = lv2;
                }
            }
            // ---- stage B half: copy pre-swizzled weight images (16KB each) ----
            {
                const uint4* wh = g_wimg[ph * 4 + half];
                const uint4* wl = g_wimg[ph * 4 + 2 + half];
                #pragma unroll
                for (int i = tid; i < 1024; i += 256) {
                    *(uint4*)(sm + OFF_BHI + i * 16) = wh[i];
                    *(uint4*)(sm + OFF_BLO + i * 16) = wl[i];
                }
            }
            __syncthreads();

            if (half == 0 && ph != 3) {
                #pragma unroll
                for (int t = 0; t < 16; t++)
                    #pragma unroll
                    for (int j = 0; j < 4; j++) acc[t][j] = 0.f;
            }

            // ---- k-loop: 4 k16 steps in this half ----
            #pragma unroll
            for (int ks = 0; ks < 4; ks++) {
                uint32_t ahi[4], alo[4];
                uint32_t achunk = (uint32_t)(((2 * ks + acsel) ^ amask) << 4);
                ldsm4(ahi, sb + OFF_AHI + aoffb + achunk);
                ldsm4(alo, sb + OFF_ALO + aoffb + achunk);
                #pragma unroll
                for (int tp = 0; tp < 8; tp++) {
                    int t0 = 2 * tp, t1 = 2 * tp + 1;
                    int brow = (tp << 4) + ((grp >> 1) << 3) + li;
                    uint32_t bo = (uint32_t)(brow * 128 + (((2 * ks + (grp & 1)) ^ (brow & 7)) << 4));
                    uint32_t bhi[4], blo[4];
                    ldsm4(bhi, sb + OFF_BHI + bo);
                    ldsm4(blo, sb + OFF_BLO + bo);
                    mma16816(acc[t0], ahi, bhi[0], bhi[1]);
                    mma16816(acc[t1], ahi, bhi[2], bhi[3]);
                    mma16816(acc[t0], ahi, blo[0], blo[1]);
                    mma16816(acc[t1], ahi, blo[2], blo[3]);
                    mma16816(acc[t0], alo, bhi[0], bhi[1]);
                    mma16816(acc[t1], alo, bhi[2], bhi[3]);
                }
            }
            __syncthreads();   // staging buffers free for reuse
        }

        if (ph == 0) {
            // ---- store K1 as fp16 (warp-private rows; same threads read in ph1) ----
            #pragma unroll
            for (int t = 0; t < 16; t++) {
                int n0 = t * 8 + dn;
                if (rA < MROWS) *(half2*)&s_k1[rA * 132 + n0] = __floats2half2_rn(acc[t][0], acc[t][1]);
                if (rB < MROWS) *(half2*)&s_k1[rB * 132 + n0] = __floats2half2_rn(acc[t][2], acc[t][3]);
            }
        } else if (ph == 1) {
            // ---- trilinear logits from K2 acc + K1(fp16 smem) + Q(smem) ----
            float part[8];
            #pragma unroll
            for (int i = 0; i < 8; i++) part[i] = 0.f;
            #pragma unroll
            for (int t = 0; t < 16; t++) {
                int h = t >> 2;
                int n0 = t * 8 + dn;
                float2 k1A = __half22float2(*(half2*)&s_k1[rA * 132 + n0]);
                float2 k1B = __half22float2(*(half2*)&s_k1[rB * 132 + n0]);
                float2 qA  = *(float2*)&s_q[gA * 128 + n0];
                float2 qB  = *(float2*)&s_q[gB * 128 + n0];
                part[h]     += qA.x * k1A.x * acc[t][0] + qA.y * k1A.y * acc[t][1];
                part[4 + h] += qB.x * k1B.x * acc[t][2] + qB.y * k1B.y * acc[t][3];
            }
            #pragma unroll
            for (int i = 0; i < 8; i++) {
                part[i] += __shfl_xor_sync(0xffffffffu, part[i], 1);
                part[i] += __shfl_xor_sync(0xffffffffu, part[i], 2);
            }
            if ((lane & 3) == 0) {
                #pragma unroll
                for (int h = 0; h < 4; h++) {
                    if (rA < MROWS) s_logit[rA * 4 + h] = part[h] * (1.0f / 32.0f);
                    if (rB < MROWS) s_logit[rB * 4 + h] = part[4 + h] * (1.0f / 32.0f);
                }
            }
            __syncthreads();
            // ---- masked softmax per (g,h), serial over 30 neighbors ----
            if (tid < 16) {
                const int g = tid >> 2, h = tid & 3;
                const float NEG = -3.4028234663852886e38f;  // float32.min, matches reference
                float m = NEG;
                for (int k = 0; k < K_; k++) {
                    float msk = s_mask[g * K_ + k];
                    float l = (msk > 0.f) ? s_logit[(g * K_ + k) * 4 + h] : NEG;
                    m = fmaxf(m, l);
                }
                float ssum = 0.f;
                for (int k = 0; k < K_; k++) {
                    float msk = s_mask[g * K_ + k];
                    float l = (msk > 0.f) ? s_logit[(g * K_ + k) * 4 + h] : NEG;
                    float e = expf(l - m);
                    s_att[(g * 4 + h) * K_ + k] = e;
                    ssum += e;
                }
                float inv = 1.0f / ssum;
                for (int k = 0; k < K_; k++)
                    s_att[(g * 4 + h) * K_ + k] *= inv * s_mask[g * K_ + k];
            }
            // s_att consumed only after phase-3's post-MMA sync
        }
    }

    // ---- scale V acc by attend, store to reduction buffer (aliases staging) ----
    {
        float aAh[4], aBh[4];
        #pragma unroll
        for (int h = 0; h < 4; h++) {
            aAh[h] = (rA < MROWS) ? s_att[(gA * 4 + h) * K_ + kA] : 0.f;
            aBh[h] = (rB < MROWS) ? s_att[(gB * 4 + h) * K_ + kB] : 0.f;
        }
        #pragma unroll
        for (int t = 0; t < 16; t++) {
            int h = t >> 2;
            int n0 = t * 8 + dn;
            if (rA < MROWS)
                *(float2*)&s_red[rA * 132 + n0] = make_float2(aAh[h] * acc[t][0], aAh[h] * acc[t][1]);
            if (rB < MROWS)
                *(float2*)&s_red[rB * 132 + n0] = make_float2(aBh[h] * acc[t][2], aBh[h] * acc[t][3]);
        }
    }
    __syncthreads();

    // ---- reduce over neighbors ----
    #pragma unroll
    for (int rep = 0; rep < 2; rep++) {
        int o = tid + rep * 256;
        int g = o >> 7, j = o & 127;
        float acc2 = 0.f;
        #pragma unroll
        for (int k = 0; k < K_; k++)
            acc2 += s_red[(g * K_ + k) * 132 + j];
        s_hupd[o] = acc2;
    }
    __syncthreads();

    // ---- output projection ----
    #pragma unroll
    for (int rep = 0; rep < 2; rep++) {
        int o = tid + rep * 256;
        int g = o >> 7, i = o & 127;
        const float4* wo = (const float4*)(W_O + (size_t)i * 128);
        const float4* hu = (const float4*)(s_hupd + g * 128);
        float acc2 = 0.f;
        #pragma unroll
        for (int c = 0; c < 32; c++) {
            float4 w = wo[c], x = hu[c];
            acc2 += w.x * x.x + w.y * x.y + w.z * x.z + w.w * x.w;
        }
        out[(size_t)(node0 + g) * 128 + i] = acc2;
    }
}

extern "C" void kernel_launch(void* const* d_in, const int* in_sizes, int n_in,
                              void* d_out, int out_size)
{
    const float* h_V  = (const float*)d_in[0];
    const float* h_EV = (const float*)d_in[1];
    const float* h_KV = (const float*)d_in[2];
    const float* h_KE = (const float*)d_in[3];
    const float* mask = (const float*)d_in[4];
    const float* W_Q  = (const float*)d_in[5];
    const float* W_K1 = (const float*)d_in[6];
    const float* W_K2 = (const float*)d_in[7];
    const float* W_V  = (const float*)d_in[8];
    const float* W_O  = (const float*)d_in[9];
    float* out = (float*)d_out;

    convert_weights_kernel<<<256, 256>>>(W_K1, W_K2, W_V);

    cudaFuncSetAttribute(neighbor_attn_hmma_kernel,
                         cudaFuncAttributeMaxDynamicSharedMemorySize, SMEM_BYTES);
    neighbor_attn_hmma_kernel<<<GRID, 256, SMEM_BYTES>>>(
        h_V, h_EV, h_KV, h_KE, mask, W_Q, W_O, out);
}

// round 7
// speedup vs baseline: 2.5109x; 1.3153x over previous
#include <cuda_runtime.h>
#include <cuda_bf16.h>
#include <cuda_fp16.h>
#include <cstdint>
#include <math.h>

// ---------------- problem constants ----------------
#define B_     4
#define N_     2000
#define K_     30
#define H_     128
#define NIN_   256
#define NODES  (B_ * N_)
#define G_     4              // nodes per CTA
#define MROWS  (G_ * K_)      // 120 valid rows of the 128-row M tile
#define GRID   (NODES / G_)   // 2000 CTAs

// ---------------- smem layout (bytes) ----------------
#define OFF_AHI   0          // A hi [128 rows x 128 bf16, 256B rows, swizzled] 32KB
#define OFF_ALO   32768      // A lo 32KB
#define OFF_K1    65536      // K1 fp16: 120 x 132 half (31680 -> pad 31744)
#define OFF_HV    97280      // 4x128 f32
#define OFF_Q     99328      // 4x128 f32
#define OFF_LOGIT 101376     // 120x4 f32
#define OFF_ATT   103424     // 16x30 f32
#define OFF_MASK  105472     // 120 f32
#define OFF_HUPD  105984     // 4x128 f32
#define SMEM_BYTES 108032
// V-reduction buffer (120 x 132 f32 = 63360) aliases A staging [0, 65536)
#define OFF_RED   0

// Weights pre-packed in mma B-fragment order:
// flat uint4 index = (((ph*2+sp)*8+ks)*2+wn)*128 + q*32 + lane
//   ph 0..3 (K1,K2,V0,V1), sp 0=hi/1=lo, ks k16-step, wn n-half, q reg-quad
__device__ uint4 g_wfrag[16384];   // 256 KB

// ---------------- helpers ----------------
static __device__ __forceinline__ uint32_t smem_u32(const void* p) {
    uint32_t a;
    asm("{ .reg .u64 t; cvta.to.shared.u64 t, %1; cvt.u32.u64 %0, t; }" : "=r"(a) : "l"(p));
    return a;
}
static __device__ __forceinline__ uint32_t pack2bf16(float a, float b) {
    __nv_bfloat162 t = __floats2bfloat162_rn(a, b);
    return *reinterpret_cast<uint32_t*>(&t);
}
static __device__ __forceinline__ void ldsm4(uint32_t* r, uint32_t addr) {
    asm volatile("ldmatrix.sync.aligned.m8n8.x4.shared.b16 {%0,%1,%2,%3}, [%4];"
                 : "=r"(r[0]), "=r"(r[1]), "=r"(r[2]), "=r"(r[3]) : "r"(addr));
}
static __device__ __forceinline__ void mma16816(float* c, const uint32_t* a, uint32_t b0, uint32_t b1) {
    asm volatile("mma.sync.aligned.m16n8k16.row.col.f32.bf16.bf16.f32 "
                 "{%0,%1,%2,%3}, {%4,%5,%6,%7}, {%8,%9}, {%0,%1,%2,%3};"
                 : "+f"(c[0]), "+f"(c[1]), "+f"(c[2]), "+f"(c[3])
                 : "r"(a[0]), "r"(a[1]), "r"(a[2]), "r"(a[3]), "r"(b0), "r"(b1));
}

// ---------------- weight pre-pack kernel (fragment order) ----------------
__global__ void convert_weights_kernel(const float* __restrict__ Wk1,
                                       const float* __restrict__ Wk2,
                                       const float* __restrict__ Wv)
{
    int idx = blockIdx.x * blockDim.x + threadIdx.x;   // 4 * 16384
    int ph = idx >> 14;
    int e = idx & 16383;
    int n = e >> 7, k = e & 127;
    float v;
    if (ph == 0)      v = Wk1[n * 128 + k];
    else if (ph == 1) v = Wk2[n * 128 + k];
    else if (ph == 2) v = Wv[n * 256 + k];
    else              v = Wv[n * 256 + 128 + k];
    __nv_bfloat16 hi = __float2bfloat16(v);
    __nv_bfloat16 lo = __float2bfloat16(v - __bfloat162float(hi));

    int ks = k >> 4, kk = k & 15;
    int wn = n >> 6, nl = n & 63;
    int nt = nl >> 3, nr = nl & 7;
    int t  = nr * 4 + ((kk & 7) >> 1);       // lane
    int rg = nt * 2 + (kk >= 8);             // reg 0..15
    int q  = rg >> 2, w = rg & 3, ee = kk & 1;

    #pragma unroll
    for (int sp = 0; sp < 2; sp++) {
        __nv_bfloat16 val = sp ? lo : hi;
        int flat = (((ph * 2 + sp) * 8 + ks) * 2 + wn) * 128 + q * 32 + t;
        *reinterpret_cast<__nv_bfloat16*>((char*)g_wfrag + (size_t)flat * 16 + w * 4 + ee * 2) = val;
    }
}

// ---------------- main fused kernel ----------------
__global__ __launch_bounds__(256, 2)
void neighbor_attn_hmma_kernel(const float* __restrict__ h_V,
                               const float* __restrict__ h_EV,
                               const float* __restrict__ h_KV,
                               const float* __restrict__ h_KE,
                               const float* __restrict__ maskg,
                               const float* __restrict__ W_Q,
                               const float* __restrict__ W_O,
                               float* __restrict__ out)
{
    extern __shared__ char sm[];
    const uint32_t sb = smem_u32(sm);
    const int tid = threadIdx.x;
    const int wid = tid >> 5;
    const int lane = tid & 31;
    const int node0 = blockIdx.x * G_;

    float*  s_red   = (float*)(sm + OFF_RED);
    __half* s_k1    = (__half*)(sm + OFF_K1);
    float*  s_hv    = (float*)(sm + OFF_HV);
    float*  s_q     = (float*)(sm + OFF_Q);
    float*  s_logit = (float*)(sm + OFF_LOGIT);
    float*  s_att   = (float*)(sm + OFF_ATT);
    float*  s_mask  = (float*)(sm + OFF_MASK);
    float*  s_hupd  = (float*)(sm + OFF_HUPD);

    // ---- load h_V rows & mask ----
    if (tid < 128) ((float4*)s_hv)[tid] = ((const float4*)(h_V + (size_t)node0 * 128))[tid];
    if (tid < MROWS) s_mask[tid] = maskg[(size_t)node0 * K_ + tid];
    __syncthreads();

    // ---- Q projection (SIMT) ----
    #pragma unroll
    for (int rep = 0; rep < 2; rep++) {
        int o = tid + rep * 256;
        int g = o >> 7, j = o & 127;
        const float4* wq = (const float4*)(W_Q + (size_t)j * 128);
        const float4* hv = (const float4*)(s_hv + g * 128);
        float acc0 = 0.f;
        #pragma unroll
        for (int d = 0; d < 32; d++) {
            float4 w = wq[d], x = hv[d];
            acc0 += w.x * x.x + w.y * x.y + w.z * x.z + w.w * x.w;
        }
        s_q[o] = acc0;
    }

    // ---- warp tiling: m32 x n64 ----
    const int wm = wid & 3;          // m-tile (rows wm*32 .. +31)
    const int wn = wid >> 2;         // n-half (cols wn*64 .. +63)
    const int qrow = lane >> 2;      // 0..7
    const int dn = (lane & 3) * 2;   // 0,2,4,6
    const int li = lane & 7;
    const int grp = lane >> 3;
    const int arow = wm * 32 + li + ((grp & 1) << 3);   // ldsm row (mt adds +16)
    const int acsel = grp >> 1;
    const int amask = arow & 7;

    // row ids for epilogues: rows[mt][rh] = wm*32 + mt*16 + rh*8 + qrow
    int rown[2][2], gof[2][2], kof[2][2];
    #pragma unroll
    for (int mt = 0; mt < 2; mt++)
        #pragma unroll
        for (int rh = 0; rh < 2; rh++) {
            int r = wm * 32 + mt * 16 + rh * 8 + qrow;
            rown[mt][rh] = r;
            gof[mt][rh] = (r < MROWS) ? (r / K_) : 0;
            kof[mt][rh] = (r < MROWS) ? (r % K_) : 0;
        }

    float acc[2][8][4];

    const float* asrc[4] = { h_KE + (size_t)node0 * 3840, h_KV + (size_t)node0 * 3840,
                             h_EV + (size_t)node0 * 7680, h_EV + (size_t)node0 * 7680 };
    const int    arst[4] = { 128, 128, 256, 256 };
    const int    acol[4] = { 0, 0, 0, 128 };

    for (int ph = 0; ph < 4; ph++) {
        // ---- stage A (full 128 cols): LDG f32 -> bf16 hi/lo -> swizzled STS ----
        {
            const float* src = asrc[ph];
            const int rs = arst[ph], co = acol[ph];
            #pragma unroll
            for (int s = tid; s < 4096; s += 256) {
                int r = s >> 5;
                int col = (s & 31) << 2;
                float4 v = make_float4(0.f, 0.f, 0.f, 0.f);
                if (r < MROWS) v = *(const float4*)(src + (size_t)r * rs + co + col);
                float hx = __bfloat162float(__float2bfloat16(v.x));
                float hy = __bfloat162float(__float2bfloat16(v.y));
                float hz = __bfloat162float(__float2bfloat16(v.z));
                float hw = __bfloat162float(__float2bfloat16(v.w));
                uint2 hv2 = make_uint2(pack2bf16(hx, hy), pack2bf16(hz, hw));
                uint2 lv2 = make_uint2(pack2bf16(v.x - hx, v.y - hy), pack2bf16(v.z - hz, v.w - hw));
                uint32_t off = (uint32_t)(r * 256 + ((((col >> 3)) ^ (r & 7)) << 4) + ((col & 7) << 1));
                *(uint2*)(sm + OFF_AHI + off) = hv2;
                *(uint2*)(sm + OFF_ALO + off) = lv2;
            }
        }
        __syncthreads();

        if (ph != 3) {
            #pragma unroll
            for (int mt = 0; mt < 2; mt++)
                #pragma unroll
                for (int nt = 0; nt < 8; nt++)
                    #pragma unroll
                    for (int j = 0; j < 4; j++) acc[mt][nt][j] = 0.f;
        }

        // ---- k-loop: 8 k16 steps, B fragments via LDG from pre-packed images ----
        #pragma unroll
        for (int ks = 0; ks < 8; ks++) {
            uint32_t ahi[2][4], alo[2][4];
            uint32_t ch = (uint32_t)(((2 * ks + acsel) ^ amask) << 4);
            #pragma unroll
            for (int mt = 0; mt < 2; mt++) {
                uint32_t ab = sb + (uint32_t)((arow + mt * 16) * 256) + ch;
                ldsm4(ahi[mt], ab + OFF_AHI);
                ldsm4(alo[mt], ab + OFF_ALO);
            }
            const uint4* bhp = g_wfrag + (((ph * 16 + ks) * 2 + wn) * 128 + lane);
            const uint4* blp = g_wfrag + (((ph * 16 + 8 + ks) * 2 + wn) * 128 + lane);
            #pragma unroll
            for (int q = 0; q < 4; q++) {
                uint4 bh = bhp[q * 32];
                uint4 bl = blp[q * 32];
                int nt0 = 2 * q, nt1 = 2 * q + 1;
                #pragma unroll
                for (int mt = 0; mt < 2; mt++) {
                    mma16816(acc[mt][nt0], ahi[mt], bh.x, bh.y);
                    mma16816(acc[mt][nt1], ahi[mt], bh.z, bh.w);
                    mma16816(acc[mt][nt0], ahi[mt], bl.x, bl.y);
                    mma16816(acc[mt][nt1], ahi[mt], bl.z, bl.w);
                    mma16816(acc[mt][nt0], alo[mt], bh.x, bh.y);
                    mma16816(acc[mt][nt1], alo[mt], bh.z, bh.w);
                }
            }
        }
        __syncthreads();   // A staging reusable / s_red writable after ph3

        if (ph == 0) {
            // ---- store K1 as fp16 (same threads read it in ph1: no barrier needed) ----
            #pragma unroll
            for (int mt = 0; mt < 2; mt++)
                #pragma unroll
                for (int nt = 0; nt < 8; nt++) {
                    int c = wn * 64 + nt * 8 + dn;
                    if (rown[mt][0] < MROWS)
                        *(half2*)&s_k1[rown[mt][0] * 132 + c] = __floats2half2_rn(acc[mt][nt][0], acc[mt][nt][1]);
                    if (rown[mt][1] < MROWS)
                        *(half2*)&s_k1[rown[mt][1] * 132 + c] = __floats2half2_rn(acc[mt][nt][2], acc[mt][nt][3]);
                }
        } else if (ph == 1) {
            // ---- trilinear logits: Q * K1 * K2 summed over this warp's 64 cols ----
            float part[2][2][2];
            #pragma unroll
            for (int mt = 0; mt < 2; mt++)
                #pragma unroll
                for (int rh = 0; rh < 2; rh++)
                    part[mt][rh][0] = part[mt][rh][1] = 0.f;
            #pragma unroll
            for (int mt = 0; mt < 2; mt++)
                #pragma unroll
                for (int nt = 0; nt < 8; nt++) {
                    int c = wn * 64 + nt * 8 + dn;
                    int hh = nt >> 2;
                    #pragma unroll
                    for (int rh = 0; rh < 2; rh++) {
                        int r = rown[mt][rh];
                        if (r < MROWS) {
                            float2 k1 = __half22float2(*(half2*)&s_k1[r * 132 + c]);
                            float2 q2 = *(float2*)&s_q[gof[mt][rh] * 128 + c];
                            part[mt][rh][hh] += q2.x * k1.x * acc[mt][nt][2 * rh]
                                              + q2.y * k1.y * acc[mt][nt][2 * rh + 1];
                        }
                    }
                }
            #pragma unroll
            for (int mt = 0; mt < 2; mt++)
                #pragma unroll
                for (int rh = 0; rh < 2; rh++)
                    #pragma unroll
                    for (int hh = 0; hh < 2; hh++) {
                        float p = part[mt][rh][hh];
                        p += __shfl_xor_sync(0xffffffffu, p, 1);
                        p += __shfl_xor_sync(0xffffffffu, p, 2);
                        if ((lane & 3) == 0 && rown[mt][rh] < MROWS)
                            s_logit[rown[mt][rh] * 4 + wn * 2 + hh] = p * (1.0f / 32.0f);
                    }
            __syncthreads();
            // ---- masked softmax per (g,h), serial over 30 neighbors ----
            if (tid < 16) {
                const int g = tid >> 2, h = tid & 3;
                const float NEG = -3.4028234663852886e38f;  // float32.min, matches reference
                float m = NEG;
                for (int k = 0; k < K_; k++) {
                    float msk = s_mask[g * K_ + k];
                    float l = (msk > 0.f) ? s_logit[(g * K_ + k) * 4 + h] : NEG;
                    m = fmaxf(m, l);
                }
                float ssum = 0.f;
                for (int k = 0; k < K_; k++) {
                    float msk = s_mask[g * K_ + k];
                    float l = (msk > 0.f) ? s_logit[(g * K_ + k) * 4 + h] : NEG;
                    float e = expf(l - m);
                    s_att[(g * 4 + h) * K_ + k] = e;
                    ssum += e;
                }
                float inv = 1.0f / ssum;
                for (int k = 0; k < K_; k++)
                    s_att[(g * 4 + h) * K_ + k] *= inv * s_mask[g * K_ + k];
            }
            // s_att consumed after ph2/ph3 staging syncs
        }
    }

    // ---- scale V acc by attend, store to reduction buffer (aliases A staging) ----
    {
        float aatt[2][2][2];
        #pragma unroll
        for (int mt = 0; mt < 2; mt++)
            #pragma unroll
            for (int rh = 0; rh < 2; rh++) {
                int r = rown[mt][rh];
                #pragma unroll
                for (int hh = 0; hh < 2; hh++)
                    aatt[mt][rh][hh] = (r < MROWS)
                        ? s_att[(gof[mt][rh] * 4 + wn * 2 + hh) * K_ + kof[mt][rh]] : 0.f;
            }
        #pragma unroll
        for (int mt = 0; mt < 2; mt++)
            #pragma unroll
            for (int nt = 0; nt < 8; nt++) {
                int c = wn * 64 + nt * 8 + dn;
                int hh = nt >> 2;
                if (rown[mt][0] < MROWS)
                    *(float2*)&s_red[rown[mt][0] * 132 + c] =
                        make_float2(aatt[mt][0][hh] * acc[mt][nt][0], aatt[mt][0][hh] * acc[mt][nt][1]);
                if (rown[mt][1] < MROWS)
                    *(float2*)&s_red[rown[mt][1] * 132 + c] =
                        make_float2(aatt[mt][1][hh] * acc[mt][nt][2], aatt[mt][1][hh] * acc[mt][nt][3]);
            }
    }
    __syncthreads();

    // ---- reduce over neighbors ----
    #pragma unroll
    for (int rep = 0; rep < 2; rep++) {
        int o = tid + rep * 256;
        int g = o >> 7, j = o & 127;
        float acc2 = 0.f;
        #pragma unroll
        for (int k = 0; k < K_; k++)
            acc2 += s_red[(g * K_ + k) * 132 + j];
        s_hupd[o] = acc2;
    }
    __syncthreads();

    // ---- output projection ----
    #pragma unroll
    for (int rep = 0; rep < 2; rep++) {
        int o = tid + rep * 256;
        int g = o >> 7, i = o & 127;
        const float4* wo = (const float4*)(W_O + (size_t)i * 128);
        const float4* hu = (const float4*)(s_hupd + g * 128);
        float acc2 = 0.f;
        #pragma unroll
        for (int c = 0; c < 32; c++) {
            float4 w = wo[c], x = hu[c];
            acc2 += w.x * x.x + w.y * x.y + w.z * x.z + w.w * x.w;
        }
        out[(size_t)(node0 + g) * 128 + i] = acc2;
    }
}

extern "C" void kernel_launch(void* const* d_in, const int* in_sizes, int n_in,
                              void* d_out, int out_size)
{
    const float* h_V  = (const float*)d_in[0];
    const float* h_EV = (const float*)d_in[1];
    const float* h_KV = (const float*)d_in[2];
    const float* h_KE = (const float*)d_in[3];
    const float* mask = (const float*)d_in[4];
    const float* W_Q  = (const float*)d_in[5];
    const float* W_K1 = (const float*)d_in[6];
    const float* W_K2 = (const float*)d_in[7];
    const float* W_V  = (const float*)d_in[8];
    const float* W_O  = (const float*)d_in[9];
    float* out = (float*)d_out;

    convert_weights_kernel<<<256, 256>>>(W_K1, W_K2, W_V);

    cudaFuncSetAttribute(neighbor_attn_hmma_kernel,
                         cudaFuncAttributeMaxDynamicSharedMemorySize, SMEM_BYTES);
    neighbor_attn_hmma_kernel<<<GRID, 256, SMEM_BYTES>>>(
        h_V, h_EV, h_KV, h_KE, mask, W_Q, W_O, out);
}

// round 8
// speedup vs baseline: 2.5645x; 1.0213x over previous
#include <cuda_runtime.h>
#include <cuda_bf16.h>
#include <cuda_fp16.h>
#include <cstdint>
#include <math.h>

// ---------------- problem constants ----------------
#define B_     4
#define N_     2000
#define K_     30
#define H_     128
#define NIN_   256
#define NODES  (B_ * N_)
#define G_     2              // nodes per CTA
#define MROWS  (G_ * K_)      // 60 valid rows of the 64-row M tile
#define GRID   (NODES / G_)   // 4000 CTAs
#define NTHR   128

// ---------------- smem layout (bytes) ----------------
#define OFF_AHI   0          // A hi [64 rows x 128 bf16, 256B rows, swizzled] 16KB
#define OFF_ALO   16384      // A lo 16KB
#define OFF_K1    32768      // K1 fp16: 60 x 132 half (15840 -> pad 16384)
#define OFF_HV    49152      // 2x128 f32
#define OFF_Q     50176      // 2x128 f32
#define OFF_LOGIT 51200      // 60x4 f32
#define OFF_ATT   52224      // 8x30 f32
#define OFF_MASK  53248      // 60 f32
#define OFF_HUPD  53504      // 2x128 f32
#define SMEM_BYTES 54528
// V-reduction buffer (60 x 132 f32 = 31680) aliases A staging [0, 32768)
#define OFF_RED   0

// Weights pre-packed in mma B-fragment order:
// flat uint4 index = (((ph*2+sp)*8+ks)*2+wn)*128 + q*32 + lane
//   ph 0..3 (K1,K2,V0,V1), sp 0=hi/1=lo, ks k16-step, wn n-half, q reg-quad
__device__ uint4 g_wfrag[16384];   // 256 KB

// ---------------- helpers ----------------
static __device__ __forceinline__ uint32_t smem_u32(const void* p) {
    uint32_t a;
    asm("{ .reg .u64 t; cvta.to.shared.u64 t, %1; cvt.u32.u64 %0, t; }" : "=r"(a) : "l"(p));
    return a;
}
static __device__ __forceinline__ uint32_t pack2bf16(float a, float b) {
    __nv_bfloat162 t = __floats2bfloat162_rn(a, b);
    return *reinterpret_cast<uint32_t*>(&t);
}
static __device__ __forceinline__ void ldsm4(uint32_t* r, uint32_t addr) {
    asm volatile("ldmatrix.sync.aligned.m8n8.x4.shared.b16 {%0,%1,%2,%3}, [%4];"
                 : "=r"(r[0]), "=r"(r[1]), "=r"(r[2]), "=r"(r[3]) : "r"(addr));
}
static __device__ __forceinline__ void mma16816(float* c, const uint32_t* a, uint32_t b0, uint32_t b1) {
    asm volatile("mma.sync.aligned.m16n8k16.row.col.f32.bf16.bf16.f32 "
                 "{%0,%1,%2,%3}, {%4,%5,%6,%7}, {%8,%9}, {%0,%1,%2,%3};"
                 : "+f"(c[0]), "+f"(c[1]), "+f"(c[2]), "+f"(c[3])
                 : "r"(a[0]), "r"(a[1]), "r"(a[2]), "r"(a[3]), "r"(b0), "r"(b1));
}

// ---------------- weight pre-pack kernel (fragment order) ----------------
__global__ void convert_weights_kernel(const float* __restrict__ Wk1,
                                       const float* __restrict__ Wk2,
                                       const float* __restrict__ Wv)
{
    int idx = blockIdx.x * blockDim.x + threadIdx.x;   // 4 * 16384
    int ph = idx >> 14;
    int e = idx & 16383;
    int n = e >> 7, k = e & 127;
    float v;
    if (ph == 0)      v = Wk1[n * 128 + k];
    else if (ph == 1) v = Wk2[n * 128 + k];
    else if (ph == 2) v = Wv[n * 256 + k];
    else              v = Wv[n * 256 + 128 + k];
    __nv_bfloat16 hi = __float2bfloat16(v);
    __nv_bfloat16 lo = __float2bfloat16(v - __bfloat162float(hi));

    int ks = k >> 4, kk = k & 15;
    int wn = n >> 6, nl = n & 63;
    int nt = nl >> 3, nr = nl & 7;
    int t  = nr * 4 + ((kk & 7) >> 1);       // lane
    int rg = nt * 2 + (kk >= 8);             // reg 0..15
    int q  = rg >> 2, w = rg & 3, ee = kk & 1;

    #pragma unroll
    for (int sp = 0; sp < 2; sp++) {
        __nv_bfloat16 val = sp ? lo : hi;
        int flat = (((ph * 2 + sp) * 8 + ks) * 2 + wn) * 128 + q * 32 + t;
        *reinterpret_cast<__nv_bfloat16*>((char*)g_wfrag + (size_t)flat * 16 + w * 4 + ee * 2) = val;
    }
}

// ---------------- main fused kernel ----------------
__global__ __launch_bounds__(NTHR, 4)
void neighbor_attn_hmma_kernel(const float* __restrict__ h_V,
                               const float* __restrict__ h_EV,
                               const float* __restrict__ h_KV,
                               const float* __restrict__ h_KE,
                               const float* __restrict__ maskg,
                               const float* __restrict__ W_Q,
                               const float* __restrict__ W_O,
                               float* __restrict__ out)
{
    extern __shared__ char sm[];
    const uint32_t sb = smem_u32(sm);
    const int tid = threadIdx.x;
    const int wid = tid >> 5;
    const int lane = tid & 31;
    const int node0 = blockIdx.x * G_;

    float*  s_red   = (float*)(sm + OFF_RED);
    __half* s_k1    = (__half*)(sm + OFF_K1);
    float*  s_hv    = (float*)(sm + OFF_HV);
    float*  s_q     = (float*)(sm + OFF_Q);
    float*  s_logit = (float*)(sm + OFF_LOGIT);
    float*  s_att   = (float*)(sm + OFF_ATT);
    float*  s_mask  = (float*)(sm + OFF_MASK);
    float*  s_hupd  = (float*)(sm + OFF_HUPD);

    // ---- load h_V rows & mask ----
    if (tid < 64) ((float4*)s_hv)[tid] = ((const float4*)(h_V + (size_t)node0 * 128))[tid];
    if (tid < MROWS) s_mask[tid] = maskg[(size_t)node0 * K_ + tid];
    __syncthreads();

    // ---- Q projection (SIMT): 2 g x 128 j = 256 outputs ----
    #pragma unroll
    for (int rep = 0; rep < 2; rep++) {
        int o = tid + rep * NTHR;
        int g = o >> 7, j = o & 127;
        const float4* wq = (const float4*)(W_Q + (size_t)j * 128);
        const float4* hv = (const float4*)(s_hv + g * 128);
        float acc0 = 0.f;
        #pragma unroll
        for (int d = 0; d < 32; d++) {
            float4 w = wq[d], x = hv[d];
            acc0 += w.x * x.x + w.y * x.y + w.z * x.z + w.w * x.w;
        }
        s_q[o] = acc0;
    }

    // ---- warp tiling: 4 warps, each m32 x n64 ----
    const int wm = wid & 1;          // m-tile (rows wm*32 .. +31)
    const int wn = wid >> 1;         // n-half (cols wn*64 .. +63)
    const int qrow = lane >> 2;      // 0..7
    const int dn = (lane & 3) * 2;   // 0,2,4,6
    const int li = lane & 7;
    const int grp = lane >> 3;
    const int arow = wm * 32 + li + ((grp & 1) << 3);   // ldsm row (mt adds +16)
    const int acsel = grp >> 1;
    const int amask = arow & 7;

    // row ids for epilogues: rows[mt][rh] = wm*32 + mt*16 + rh*8 + qrow
    int rown[2][2], gof[2][2], kof[2][2];
    #pragma unroll
    for (int mt = 0; mt < 2; mt++)
        #pragma unroll
        for (int rh = 0; rh < 2; rh++) {
            int r = wm * 32 + mt * 16 + rh * 8 + qrow;
            rown[mt][rh] = r;
            gof[mt][rh] = (r < MROWS) ? (r / K_) : 0;
            kof[mt][rh] = (r < MROWS) ? (r % K_) : 0;
        }

    float acc[2][8][4];

    const float* asrc[4] = { h_KE + (size_t)node0 * 3840, h_KV + (size_t)node0 * 3840,
                             h_EV + (size_t)node0 * 7680, h_EV + (size_t)node0 * 7680 };
    const int    arst[4] = { 128, 128, 256, 256 };
    const int    acol[4] = { 0, 0, 0, 128 };

    for (int ph = 0; ph < 4; ph++) {
        // ---- stage A (64 rows x 128 cols): LDG f32 -> bf16 hi/lo -> swizzled STS ----
        {
            const float* src = asrc[ph];
            const int rs = arst[ph], co = acol[ph];
            #pragma unroll
            for (int s = tid; s < 2048; s += NTHR) {
                int r = s >> 5;
                int col = (s & 31) << 2;
                float4 v = make_float4(0.f, 0.f, 0.f, 0.f);
                if (r < MROWS) v = *(const float4*)(src + (size_t)r * rs + co + col);
                float hx = __bfloat162float(__float2bfloat16(v.x));
                float hy = __bfloat162float(__float2bfloat16(v.y));
                float hz = __bfloat162float(__float2bfloat16(v.z));
                float hw = __bfloat162float(__float2bfloat16(v.w));
                uint2 hv2 = make_uint2(pack2bf16(hx, hy), pack2bf16(hz, hw));
                uint2 lv2 = make_uint2(pack2bf16(v.x - hx, v.y - hy), pack2bf16(v.z - hz, v.w - hw));
                uint32_t off = (uint32_t)(r * 256 + ((((col >> 3)) ^ (r & 7)) << 4) + ((col & 7) << 1));
                *(uint2*)(sm + OFF_AHI + off) = hv2;
                *(uint2*)(sm + OFF_ALO + off) = lv2;
            }
        }
        __syncthreads();

        if (ph != 3) {
            #pragma unroll
            for (int mt = 0; mt < 2; mt++)
                #pragma unroll
                for (int nt = 0; nt < 8; nt++)
                    #pragma unroll
                    for (int j = 0; j < 4; j++) acc[mt][nt][j] = 0.f;
        }

        // ---- k-loop: 8 k16 steps, B fragments via LDG from pre-packed images ----
        #pragma unroll
        for (int ks = 0; ks < 8; ks++) {
            uint32_t ahi[2][4], alo[2][4];
            uint32_t ch = (uint32_t)(((2 * ks + acsel) ^ amask) << 4);
            #pragma unroll
            for (int mt = 0; mt < 2; mt++) {
                uint32_t ab = sb + (uint32_t)((arow + mt * 16) * 256) + ch;
                ldsm4(ahi[mt], ab + OFF_AHI);
                ldsm4(alo[mt], ab + OFF_ALO);
            }
            const uint4* bhp = g_wfrag + (((ph * 16 + ks) * 2 + wn) * 128 + lane);
            const uint4* blp = g_wfrag + (((ph * 16 + 8 + ks) * 2 + wn) * 128 + lane);
            #pragma unroll
            for (int q = 0; q < 4; q++) {
                uint4 bh = bhp[q * 32];
                uint4 bl = blp[q * 32];
                int nt0 = 2 * q, nt1 = 2 * q + 1;
                #pragma unroll
                for (int mt = 0; mt < 2; mt++) {
                    mma16816(acc[mt][nt0], ahi[mt], bh.x, bh.y);
                    mma16816(acc[mt][nt1], ahi[mt], bh.z, bh.w);
                    mma16816(acc[mt][nt0], ahi[mt], bl.x, bl.y);
                    mma16816(acc[mt][nt1], ahi[mt], bl.z, bl.w);
                    mma16816(acc[mt][nt0], alo[mt], bh.x, bh.y);
                    mma16816(acc[mt][nt1], alo[mt], bh.z, bh.w);
                }
            }
        }
        __syncthreads();   // A staging reusable / s_red writable after ph3

        if (ph == 0) {
            // ---- store K1 as fp16 (warp-private rows; same threads read in ph1) ----
            #pragma unroll
            for (int mt = 0; mt < 2; mt++)
                #pragma unroll
                for (int nt = 0; nt < 8; nt++) {
                    int c = wn * 64 + nt * 8 + dn;
                    if (rown[mt][0] < MROWS)
                        *(half2*)&s_k1[rown[mt][0] * 132 + c] = __floats2half2_rn(acc[mt][nt][0], acc[mt][nt][1]);
                    if (rown[mt][1] < MROWS)
                        *(half2*)&s_k1[rown[mt][1] * 132 + c] = __floats2half2_rn(acc[mt][nt][2], acc[mt][nt][3]);
                }
        } else if (ph == 1) {
            // ---- trilinear logits: Q * K1 * K2 summed over this warp's 64 cols ----
            float part[2][2][2];
            #pragma unroll
            for (int mt = 0; mt < 2; mt++)
                #pragma unroll
                for (int rh = 0; rh < 2; rh++)
                    part[mt][rh][0] = part[mt][rh][1] = 0.f;
            #pragma unroll
            for (int mt = 0; mt < 2; mt++)
                #pragma unroll
                for (int nt = 0; nt < 8; nt++) {
                    int c = wn * 64 + nt * 8 + dn;
                    int hh = nt >> 2;
                    #pragma unroll
                    for (int rh = 0; rh < 2; rh++) {
                        int r = rown[mt][rh];
                        if (r < MROWS) {
                            float2 k1 = __half22float2(*(half2*)&s_k1[r * 132 + c]);
                            float2 q2 = *(float2*)&s_q[gof[mt][rh] * 128 + c];
                            part[mt][rh][hh] += q2.x * k1.x * acc[mt][nt][2 * rh]
                                              + q2.y * k1.y * acc[mt][nt][2 * rh + 1];
                        }
                    }
                }
            #pragma unroll
            for (int mt = 0; mt < 2; mt++)
                #pragma unroll
                for (int rh = 0; rh < 2; rh++)
                    #pragma unroll
                    for (int hh = 0; hh < 2; hh++) {
                        float p = part[mt][rh][hh];
                        p += __shfl_xor_sync(0xffffffffu, p, 1);
                        p += __shfl_xor_sync(0xffffffffu, p, 2);
                        if ((lane & 3) == 0 && rown[mt][rh] < MROWS)
                            s_logit[rown[mt][rh] * 4 + wn * 2 + hh] = p * (1.0f / 32.0f);
                    }
            __syncthreads();
            // ---- masked softmax per (g,h), serial over 30 neighbors ----
            if (tid < 8) {
                const int g = tid >> 2, h = tid & 3;
                const float NEG = -3.4028234663852886e38f;  // float32.min, matches reference
                float m = NEG;
                for (int k = 0; k < K_; k++) {
                    float msk = s_mask[g * K_ + k];
                    float l = (msk > 0.f) ? s_logit[(g * K_ + k) * 4 + h] : NEG;
                    m = fmaxf(m, l);
                }
                float ssum = 0.f;
                for (int k = 0; k < K_; k++) {
                    float msk = s_mask[g * K_ + k];
                    float l = (msk > 0.f) ? s_logit[(g * K_ + k) * 4 + h] : NEG;
                    float e = expf(l - m);
                    s_att[(g * 4 + h) * K_ + k] = e;
                    ssum += e;
                }
                float inv = 1.0f / ssum;
                for (int k = 0; k < K_; k++)
                    s_att[(g * 4 + h) * K_ + k] *= inv * s_mask[g * K_ + k];
            }
            // s_att consumed after ph2/ph3 staging syncs
        }
    }

    // ---- scale V acc by attend, store to reduction buffer (aliases A staging) ----
    {
        float aatt[2][2][2];
        #pragma unroll
        for (int mt = 0; mt < 2; mt++)
            #pragma unroll
            for (int rh = 0; rh < 2; rh++) {
                int r = rown[mt][rh];
                #pragma unroll
                for (int hh = 0; hh < 2; hh++)
                    aatt[mt][rh][hh] = (r < MROWS)
                        ? s_att[(gof[mt][rh] * 4 + wn * 2 + hh) * K_ + kof[mt][rh]] : 0.f;
            }
        #pragma unroll
        for (int mt = 0; mt < 2; mt++)
            #pragma unroll
            for (int nt = 0; nt < 8; nt++) {
                int c = wn * 64 + nt * 8 + dn;
                int hh = nt >> 2;
                if (rown[mt][0] < MROWS)
                    *(float2*)&s_red[rown[mt][0] * 132 + c] =
                        make_float2(aatt[mt][0][hh] * acc[mt][nt][0], aatt[mt][0][hh] * acc[mt][nt][1]);
                if (rown[mt][1] < MROWS)
                    *(float2*)&s_red[rown[mt][1] * 132 + c] =
                        make_float2(aatt[mt][1][hh] * acc[mt][nt][2], aatt[mt][1][hh] * acc[mt][nt][3]);
            }
    }
    __syncthreads();

    // ---- reduce over neighbors: h_upd[g][j] = sum_k red[g*30+k][j] ----
    #pragma unroll
    for (int rep = 0; rep < 2; rep++) {
        int o = tid + rep * NTHR;
        int g = o >> 7, j = o & 127;
        float acc2 = 0.f;
        #pragma unroll
        for (int k = 0; k < K_; k++)
            acc2 += s_red[(g * K_ + k) * 132 + j];
        s_hupd[o] = acc2;
    }
    __syncthreads();

    // ---- output projection ----
    #pragma unroll
    for (int rep = 0; rep < 2; rep++) {
        int o = tid + rep * NTHR;
        int g = o >> 7, i = o & 127;
        const float4* wo = (const float4*)(W_O + (size_t)i * 128);
        const float4* hu = (const float4*)(s_hupd + g * 128);
        float acc2 = 0.f;
        #pragma unroll
        for (int c = 0; c < 32; c++) {
            float4 w = wo[c], x = hu[c];
            acc2 += w.x * x.x + w.y * x.y + w.z * x.z + w.w * x.w;
        }
        out[(size_t)(node0 + g) * 128 + i] = acc2;
    }
}

extern "C" void kernel_launch(void* const* d_in, const int* in_sizes, int n_in,
                              void* d_out, int out_size)
{
    const float* h_V  = (const float*)d_in[0];
    const float* h_EV = (const float*)d_in[1];
    const float* h_KV = (const float*)d_in[2];
    const float* h_KE = (const float*)d_in[3];
    const float* mask = (const float*)d_in[4];
    const float* W_Q  = (const float*)d_in[5];
    const float* W_K1 = (const float*)d_in[6];
    const float* W_K2 = (const float*)d_in[7];
    const float* W_V  = (const float*)d_in[8];
    const float* W_O  = (const float*)d_in[9];
    float* out = (float*)d_out;

    convert_weights_kernel<<<256, 256>>>(W_K1, W_K2, W_V);

    cudaFuncSetAttribute(neighbor_attn_hmma_kernel,
                         cudaFuncAttributeMaxDynamicSharedMemorySize, SMEM_BYTES);
    neighbor_attn_hmma_kernel<<<GRID, NTHR, SMEM_BYTES>>>(
        h_V, h_EV, h_KV, h_KE, mask, W_Q, W_O, out);
}

// round 10
// speedup vs baseline: 2.7354x; 1.0667x over previous
#include <cuda_runtime.h>
#include <cuda_bf16.h>
#include <cuda_fp16.h>
#include <cstdint>
#include <math.h>

// ---------------- problem constants ----------------
#define B_     4
#define N_     2000
#define K_     30
#define H_     128
#define NIN_   256
#define NODES  (B_ * N_)
#define G_     2              // nodes per CTA
#define MROWS  (G_ * K_)      // 60 valid rows of the 64-row M tile
#define GRID   (NODES / G_)   // 4000 CTAs
#define NTHR   256

// ---------------- smem layout (bytes) ----------------
// A staged as raw f32 [64 rows x 128 f32 = 512B rows], XOR-swizzled 8B granules
#define OFF_BUF0  0          // 32KB
#define OFF_BUF1  32768      // 32KB
#define OFF_K1    65536      // K1 fp16: 60 x 132 half = 15840 (pad to 16000)
#define OFF_HV    81536      // 2x128 f32
#define OFF_Q     82560      // 2x128 f32
#define OFF_LOGIT 83584      // 60x4 f32
#define OFF_ATT   84608      // 8x30 f32
#define OFF_MASK  85632      // 60 f32
#define OFF_HUPD  85888      // 2x128 f32
#define SMEM_BYTES 86912
// V-reduction buffer (60 x 132 f32 = 31680) aliases BUF0
#define OFF_RED   0

// Weights pre-packed in mma B-fragment order (n32 granularity):
// flat uint4 = (ph*2+sp)*2048 + ks*256 + wn32*64 + qh*32 + lane
__device__ uint4 g_wfrag[16384];   // 256 KB

// ---------------- helpers ----------------
static __device__ __forceinline__ uint32_t smem_u32(const void* p) {
    uint32_t a;
    asm("{ .reg .u64 t; cvta.to.shared.u64 t, %1; cvt.u32.u64 %0, t; }" : "=r"(a) : "l"(p));
    return a;
}
static __device__ __forceinline__ void mma16816(float* c, const uint32_t* a, uint32_t b0, uint32_t b1) {
    asm volatile("mma.sync.aligned.m16n8k16.row.col.f32.bf16.bf16.f32 "
                 "{%0,%1,%2,%3}, {%4,%5,%6,%7}, {%8,%9}, {%0,%1,%2,%3};"
                 : "+f"(c[0]), "+f"(c[1]), "+f"(c[2]), "+f"(c[3])
                 : "r"(a[0]), "r"(a[1]), "r"(a[2]), "r"(a[3]), "r"(b0), "r"(b1));
}
static __device__ __forceinline__ void cvt_split(float2 v, uint32_t& hi, uint32_t& lo) {
    __nv_bfloat162 h2 = __floats2bfloat162_rn(v.x, v.y);
    float hx = __bfloat162float(h2.x), hy = __bfloat162float(h2.y);
    __nv_bfloat162 l2 = __floats2bfloat162_rn(v.x - hx, v.y - hy);
    hi = *(uint32_t*)&h2;
    lo = *(uint32_t*)&l2;
}
#define CP_ASYNC8(dst, src, sz) \
    asm volatile("cp.async.ca.shared.global [%0], [%1], 8, %2;" :: "r"(dst), "l"(src), "r"(sz) : "memory")
#define CP_COMMIT()  asm volatile("cp.async.commit_group;" ::: "memory")
#define CP_WAIT0()   asm volatile("cp.async.wait_group 0;" ::: "memory")

// ---------------- weight pre-pack kernel (fragment order, n32 blocks) ----------------
__global__ void convert_weights_kernel(const float* __restrict__ Wk1,
                                       const float* __restrict__ Wk2,
                                       const float* __restrict__ Wv)
{
    int idx = blockIdx.x * blockDim.x + threadIdx.x;   // 4 * 16384
    int ph = idx >> 14;
    int e = idx & 16383;
    int n = e >> 7, k = e & 127;
    float v;
    if (ph == 0)      v = Wk1[n * 128 + k];
    else if (ph == 1) v = Wk2[n * 128 + k];
    else if (ph == 2) v = Wv[n * 256 + k];
    else              v = Wv[n * 256 + 128 + k];
    __nv_bfloat16 hi = __float2bfloat16(v);
    __nv_bfloat16 lo = __float2bfloat16(v - __bfloat162float(hi));

    int ks = k >> 4, kk = k & 15;
    int wn = n >> 5, nl = n & 31;
    int nt = nl >> 3, nr = nl & 7;
    int t  = nr * 4 + ((kk & 7) >> 1);        // lane
    int rg = (nt & 1) * 2 + (kk >= 8);        // word in uint4
    int qh = nt >> 1;
    int ee = kk & 1;

    #pragma unroll
    for (int sp = 0; sp < 2; sp++) {
        __nv_bfloat16 val = sp ? lo : hi;
        int flat = (ph * 2 + sp) * 2048 + ks * 256 + wn * 64 + qh * 32 + t;
        *reinterpret_cast<__nv_bfloat16*>((char*)g_wfrag + (size_t)flat * 16 + rg * 4 + ee * 2) = val;
    }
}

// ---------------- main fused kernel ----------------
__global__ __launch_bounds__(NTHR, 2)
void neighbor_attn_hmma_kernel(const float* __restrict__ h_V,
                               const float* __restrict__ h_EV,
                               const float* __restrict__ h_KV,
                               const float* __restrict__ h_KE,
                               const float* __restrict__ maskg,
                               const float* __restrict__ W_Q,
                               const float* __restrict__ W_O,
                               float* __restrict__ out)
{
    extern __shared__ char sm[];
    const uint32_t sb = smem_u32(sm);
    const int tid = threadIdx.x;
    const int wid = tid >> 5;
    const int lane = tid & 31;
    const int node0 = blockIdx.x * G_;

    float*  s_red   = (float*)(sm + OFF_RED);
    __half* s_k1    = (__half*)(sm + OFF_K1);
    float*  s_hv    = (float*)(sm + OFF_HV);
    float*  s_q     = (float*)(sm + OFF_Q);
    float*  s_logit = (float*)(sm + OFF_LOGIT);
    float*  s_att   = (float*)(sm + OFF_ATT);
    float*  s_mask  = (float*)(sm + OFF_MASK);
    float*  s_hupd  = (float*)(sm + OFF_HUPD);

    const float* asrc[4] = { h_KE + (size_t)node0 * 3840, h_KV + (size_t)node0 * 3840,
                             h_EV + (size_t)node0 * 7680, h_EV + (size_t)node0 * 7680 };
    const int    arst[4] = { 128, 128, 256, 256 };
    const int    acol[4] = { 0, 0, 0, 128 };

    // stage phase ph_'s A tile (raw f32, swizzled 8B granules) into buffer bufo
    auto stage = [&](int ph_, uint32_t bufo) {
        const float* src = asrc[ph_];
        const int rs = arst[ph_], co = acol[ph_];
        #pragma unroll
        for (int s = tid; s < 4096; s += NTHR) {
            int r = s >> 6, gg = s & 63;
            uint32_t dst = sb + bufo + (uint32_t)(r * 512 + ((gg ^ ((r & 3) << 2)) << 3));
            int rr = (r < MROWS) ? r : 0;
            const float* sp_ = src + (size_t)rr * rs + co + 2 * gg;
            uint32_t sz = (r < MROWS) ? 8u : 0u;
            CP_ASYNC8(dst, sp_, sz);
        }
        CP_COMMIT();
    };

    // ---- prologue: kick off ph0 staging, then do Q projection under it ----
    stage(0, OFF_BUF0);

    if (tid < 64) ((float4*)s_hv)[tid] = ((const float4*)(h_V + (size_t)node0 * 128))[tid];
    if (tid < MROWS) s_mask[tid] = maskg[(size_t)node0 * K_ + tid];
    __syncthreads();

    {   // Q[g][j], 256 outputs
        int g = tid >> 7, j = tid & 127;
        const float4* wq = (const float4*)(W_Q + (size_t)j * 128);
        const float4* hv = (const float4*)(s_hv + g * 128);
        float acc0 = 0.f;
        #pragma unroll
        for (int d = 0; d < 32; d++) {
            float4 w = wq[d], x = hv[d];
            acc0 += w.x * x.x + w.y * x.y + w.z * x.z + w.w * x.w;
        }
        s_q[tid] = acc0;
    }

    // ---- warp tiling: 8 warps, each m32 x n32 ----
    const int wm = wid & 1;          // m-tile: rows wm*32 .. +31
    const int wn = wid >> 1;         // n32 block == head wn
    const int qrow = lane >> 2;      // 0..7
    const int pA   = lane & 3;
    const int dn   = pA * 2;
    const uint32_t swA = (uint32_t)((qrow & 3) << 2);
    const uint32_t arowb = (uint32_t)((wm * 32 + qrow) * 512);

    int rown[2][2], gof[2][2], kof[2][2];
    #pragma unroll
    for (int mt = 0; mt < 2; mt++)
        #pragma unroll
        for (int rh = 0; rh < 2; rh++) {
            int r = wm * 32 + mt * 16 + rh * 8 + qrow;
            rown[mt][rh] = r;
            gof[mt][rh] = (r < MROWS) ? (r / K_) : 0;
            kof[mt][rh] = (r < MROWS) ? (r % K_) : 0;
        }

    float acc[2][4][4];

    CP_WAIT0();
    __syncthreads();   // ph0 A tile visible

    for (int ph = 0; ph < 4; ph++) {
        // kick off next phase's staging into the other buffer
        if (ph < 3) stage(ph + 1, (uint32_t)(((ph + 1) & 1) ? OFF_BUF1 : OFF_BUF0));

        const uint32_t bufr = (uint32_t)((ph & 1) ? OFF_BUF1 : OFF_BUF0);

        if (ph != 3) {
            #pragma unroll
            for (int mt = 0; mt < 2; mt++)
                #pragma unroll
                for (int nt = 0; nt < 4; nt++)
                    #pragma unroll
                    for (int j = 0; j < 4; j++) acc[mt][nt][j] = 0.f;
        }

        // ---- k-loop: 8 k16 steps ----
        #pragma unroll
        for (int ks = 0; ks < 8; ks++) {
            // B fragments (L2-hot, fragment-ordered)
            const uint4* bb = g_wfrag + (ph * 2) * 2048 + ks * 256 + wn * 64 + lane;
            uint4 bh0 = __ldg(bb);
            uint4 bh1 = __ldg(bb + 32);
            uint4 bl0 = __ldg(bb + 2048);
            uint4 bl1 = __ldg(bb + 2048 + 32);

            // A fragments: f32 pairs from swizzled smem -> split bf16 hi/lo
            uint32_t g0 = (uint32_t)((((uint32_t)(ks * 8 + pA)) ^ swA) << 3);
            uint32_t g1 = (uint32_t)((((uint32_t)(ks * 8 + 4 + pA)) ^ swA) << 3);
            uint32_t ahi[2][4], alo[2][4];
            #pragma unroll
            for (int mt = 0; mt < 2; mt++) {
                const char* rb = sm + bufr + arowb + (uint32_t)(mt * 16 * 512);
                float2 v;
                v = *(const float2*)(rb + g0);            cvt_split(v, ahi[mt][0], alo[mt][0]);
                v = *(const float2*)(rb + 8 * 512 + g0);  cvt_split(v, ahi[mt][1], alo[mt][1]);
                v = *(const float2*)(rb + g1);            cvt_split(v, ahi[mt][2], alo[mt][2]);
                v = *(const float2*)(rb + 8 * 512 + g1);  cvt_split(v, ahi[mt][3], alo[mt][3]);
            }
            #pragma unroll
            for (int mt = 0; mt < 2; mt++) {
                mma16816(acc[mt][0], ahi[mt], bh0.x, bh0.y);
                mma16816(acc[mt][1], ahi[mt], bh0.z, bh0.w);
                mma16816(acc[mt][2], ahi[mt], bh1.x, bh1.y);
                mma16816(acc[mt][3], ahi[mt], bh1.z, bh1.w);
                mma16816(acc[mt][0], ahi[mt], bl0.x, bl0.y);
                mma16816(acc[mt][1], ahi[mt], bl0.z, bl0.w);
                mma16816(acc[mt][2], ahi[mt], bl1.x, bl1.y);
                mma16816(acc[mt][3], ahi[mt], bl1.z, bl1.w);
                mma16816(acc[mt][0], alo[mt], bh0.x, bh0.y);
                mma16816(acc[mt][1], alo[mt], bh0.z, bh0.w);
                mma16816(acc[mt][2], alo[mt], bh1.x, bh1.y);
                mma16816(acc[mt][3], alo[mt], bh1.z, bh1.w);
            }
        }

        if (ph == 0) {
            // ---- store K1 as fp16 (rows & cols warp-private; same warp reads in ph1) ----
            #pragma unroll
            for (int mt = 0; mt < 2; mt++)
                #pragma unroll
                for (int nt = 0; nt < 4; nt++) {
                    int c = wn * 32 + nt * 8 + dn;
                    if (rown[mt][0] < MROWS)
                        *(half2*)&s_k1[rown[mt][0] * 132 + c] = __floats2half2_rn(acc[mt][nt][0], acc[mt][nt][1]);
                    if (rown[mt][1] < MROWS)
                        *(half2*)&s_k1[rown[mt][1] * 132 + c] = __floats2half2_rn(acc[mt][nt][2], acc[mt][nt][3]);
                }
        } else if (ph == 1) {
            // ---- trilinear logits for head wn over this warp's 32 cols ----
            float part[2][2];
            part[0][0] = part[0][1] = part[1][0] = part[1][1] = 0.f;
            #pragma unroll
            for (int mt = 0; mt < 2; mt++)
                #pragma unroll
                for (int nt = 0; nt < 4; nt++) {
                    int c = wn * 32 + nt * 8 + dn;
                    #pragma unroll
                    for (int rh = 0; rh < 2; rh++) {
                        int r = rown[mt][rh];
                        if (r < MROWS) {
                            float2 k1 = __half22float2(*(half2*)&s_k1[r * 132 + c]);
                            float2 q2 = *(float2*)&s_q[gof[mt][rh] * 128 + c];
                            part[mt][rh] += q2.x * k1.x * acc[mt][nt][2 * rh]
                                          + q2.y * k1.y * acc[mt][nt][2 * rh + 1];
                        }
                    }
                }
            #pragma unroll
            for (int mt = 0; mt < 2; mt++)
                #pragma unroll
                for (int rh = 0; rh < 2; rh++) {
                    float p = part[mt][rh];
                    p += __shfl_xor_sync(0xffffffffu, p, 1);
                    p += __shfl_xor_sync(0xffffffffu, p, 2);
                    if ((lane & 3) == 0 && rown[mt][rh] < MROWS)
                        s_logit[rown[mt][rh] * 4 + wn] = p * (1.0f / 32.0f);
                }
            __syncthreads();
            // ---- masked softmax per (g,h) ----
            if (tid < 8) {
                const int g = tid >> 2, h = tid & 3;
                const float NEG = -3.4028234663852886e38f;  // float32.min, matches reference
                float m = NEG;
                for (int k = 0; k < K_; k++) {
                    float msk = s_mask[g * K_ + k];
                    float l = (msk > 0.f) ? s_logit[(g * K_ + k) * 4 + h] : NEG;
                    m = fmaxf(m, l);
                }
                float ssum = 0.f;
                for (int k = 0; k < K_; k++) {
                    float msk = s_mask[g * K_ + k];
                    float l = (msk > 0.f) ? s_logit[(g * K_ + k) * 4 + h] : NEG;
                    float e = expf(l - m);
                    s_att[(g * 4 + h) * K_ + k] = e;
                    ssum += e;
                }
                float inv = 1.0f / ssum;
                for (int k = 0; k < K_; k++)
                    s_att[(g * 4 + h) * K_ + k] *= inv * s_mask[g * K_ + k];
            }
            __syncthreads();   // s_att visible to all
        }

        // next phase's tile must be resident before its k-loop
        CP_WAIT0();
        __syncthreads();
    }

    // ---- scale V acc by attend (head = wn), store to reduction buffer (aliases BUF0) ----
    {
        float aatt[2][2];
        #pragma unroll
        for (int mt = 0; mt < 2; mt++)
            #pragma unroll
            for (int rh = 0; rh < 2; rh++)
                aatt[mt][rh] = (rown[mt][rh] < MROWS)
                    ? s_att[(gof[mt][rh] * 4 + wn) * K_ + kof[mt][rh]] : 0.f;
        #pragma unroll
        for (int mt = 0; mt < 2; mt++)
            #pragma unroll
            for (int nt = 0; nt < 4; nt++) {
                int c = wn * 32 + nt * 8 + dn;
                if (rown[mt][0] < MROWS)
                    *(float2*)&s_red[rown[mt][0] * 132 + c] =
                        make_float2(aatt[mt][0] * acc[mt][nt][0], aatt[mt][0] * acc[mt][nt][1]);
                if (rown[mt][1] < MROWS)
                    *(float2*)&s_red[rown[mt][1] * 132 + c] =
                        make_float2(aatt[mt][1] * acc[mt][nt][2], aatt[mt][1] * acc[mt][nt][3]);
            }
    }
    __syncthreads();

    // ---- reduce over neighbors: h_upd[g][j] = sum_k red[g*30+k][j] ----
    {
        int g = tid >> 7, j = tid & 127;
        float acc2 = 0.f;
        #pragma unroll
        for (int k = 0; k < K_; k++)
            acc2 += s_red[(g * K_ + k) * 132 + j];
        s_hupd[tid] = acc2;
    }
    __syncthreads();

    // ---- output projection ----
    {
        int g = tid >> 7, i = tid & 127;
        const float4* wo = (const float4*)(W_O + (size_t)i * 128);
        const float4* hu = (const float4*)(s_hupd + g * 128);
        float acc2 = 0.f;
        #pragma unroll
        for (int c = 0; c < 32; c++) {
            float4 w = wo[c], x = hu[c];
            acc2 += w.x * x.x + w.y * x.y + w.z * x.z + w.w * x.w;
        }
        out[(size_t)(node0 + g) * 128 + i] = acc2;
    }
}

extern "C" void kernel_launch(void* const* d_in, const int* in_sizes, int n_in,
                              void* d_out, int out_size)
{
    const float* h_V  = (const float*)d_in[0];
    const float* h_EV = (const float*)d_in[1];
    const float* h_KV = (const float*)d_in[2];
    const float* h_KE = (const float*)d_in[3];
    const float* mask = (const float*)d_in[4];
    const float* W_Q  = (const float*)d_in[5];
    const float* W_K1 = (const float*)d_in[6];
    const float* W_K2 = (const float*)d_in[7];
    const float* W_V  = (const float*)d_in[8];
    const float* W_O  = (const float*)d_in[9];
    float* out = (float*)d_out;

    convert_weights_kernel<<<256, 256>>>(W_K1, W_K2, W_V);

    cudaFuncSetAttribute(neighbor_attn_hmma_kernel,
                         cudaFuncAttributeMaxDynamicSharedMemorySize, SMEM_BYTES);
    neighbor_attn_hmma_kernel<<<GRID, NTHR, SMEM_BYTES>>>(
        h_V, h_EV, h_KV, h_KE, mask, W_Q, W_O, out);
}

// round 12
// speedup vs baseline: 3.3486x; 1.2242x over previous
#include <cuda_runtime.h>
#include <cuda_bf16.h>
#include <cuda_fp16.h>
#include <cstdint>
#include <math.h>

// ---------------- problem constants ----------------
#define B_     4
#define N_     2000
#define K_     30
#define H_     128
#define NIN_   256
#define NODES  (B_ * N_)
#define G_     2              // nodes per CTA
#define MROWS  (G_ * K_)      // 60 valid rows of the 64-row M tile
#define GRID   (NODES / G_)   // 4000 CTAs
#define NTHR   256

// ---------------- smem layout (bytes) ----------------
// A staged as raw f32 [64 rows x 128 f32 = 512B rows], XOR-swizzled 8B granules
#define OFF_BUF0  0          // 32KB
#define OFF_BUF1  32768      // 32KB
#define OFF_K1    65536      // K1 fp16: 60 x 132 half = 15840 (pad to 16000)
#define OFF_HV    81536      // 2x128 f32
#define OFF_Q     82560      // 2x128 f32
#define OFF_LOGIT 83584      // 60x4 f32
#define OFF_ATT   84608      // 8x30 f32
#define OFF_MASK  85632      // 60 f32
#define OFF_HUPD  85888      // 2x128 f32
#define SMEM_BYTES 86912
// V-reduction buffer (60 x 132 f32 = 31680) aliases BUF0
#define OFF_RED   0

// Weights pre-packed as fp16 in mma B-fragment order (n32 granularity):
// flat uint4 = ph*2048 + ks*256 + wn32*64 + qh*32 + lane
__device__ uint4 g_wfrag[8192];   // 128 KB

// ---------------- helpers ----------------
static __device__ __forceinline__ uint32_t smem_u32(const void* p) {
    uint32_t a;
    asm("{ .reg .u64 t; cvta.to.shared.u64 t, %1; cvt.u32.u64 %0, t; }" : "=r"(a) : "l"(p));
    return a;
}
static __device__ __forceinline__ void mma16816f(float* c, const uint32_t* a, uint32_t b0, uint32_t b1) {
    asm volatile("mma.sync.aligned.m16n8k16.row.col.f32.f16.f16.f32 "
                 "{%0,%1,%2,%3}, {%4,%5,%6,%7}, {%8,%9}, {%0,%1,%2,%3};"
                 : "+f"(c[0]), "+f"(c[1]), "+f"(c[2]), "+f"(c[3])
                 : "r"(a[0]), "r"(a[1]), "r"(a[2]), "r"(a[3]), "r"(b0), "r"(b1));
}
static __device__ __forceinline__ uint32_t pack2h(float2 v) {
    __half2 t = __floats2half2_rn(v.x, v.y);
    return *reinterpret_cast<uint32_t*>(&t);
}
#define CP_ASYNC8(dst, src, sz) \
    asm volatile("cp.async.ca.shared.global [%0], [%1], 8, %2;" :: "r"(dst), "l"(src), "r"(sz) : "memory")
#define CP_COMMIT()  asm volatile("cp.async.commit_group;" ::: "memory")
#define CP_WAIT0()   asm volatile("cp.async.wait_group 0;" ::: "memory")

// ---------------- weight pre-pack kernel (fp16, fragment order, n32 blocks) ----------------
__global__ void convert_weights_kernel(const float* __restrict__ Wk1,
                                       const float* __restrict__ Wk2,
                                       const float* __restrict__ Wv)
{
    int idx = blockIdx.x * blockDim.x + threadIdx.x;   // 4 * 16384
    int ph = idx >> 14;
    int e = idx & 16383;
    int n = e >> 7, k = e & 127;
    float v;
    if (ph == 0)      v = Wk1[n * 128 + k];
    else if (ph == 1) v = Wk2[n * 128 + k];
    else if (ph == 2) v = Wv[n * 256 + k];
    else              v = Wv[n * 256 + 128 + k];
    __half h = __float2half(v);

    int ks = k >> 4, kk = k & 15;
    int wn = n >> 5, nl = n & 31;
    int nt = nl >> 3, nr = nl & 7;
    int t  = nr * 4 + ((kk & 7) >> 1);        // lane
    int rg = (nt & 1) * 2 + (kk >= 8);        // word in uint4
    int qh = nt >> 1;
    int ee = kk & 1;

    int flat = ph * 2048 + ks * 256 + wn * 64 + qh * 32 + t;
    *reinterpret_cast<__half*>((char*)g_wfrag + (size_t)flat * 16 + rg * 4 + ee * 2) = h;
}

// ---------------- main fused kernel ----------------
__global__ __launch_bounds__(NTHR, 2)
void neighbor_attn_hmma_kernel(const float* __restrict__ h_V,
                               const float* __restrict__ h_EV,
                               const float* __restrict__ h_KV,
                               const float* __restrict__ h_KE,
                               const float* __restrict__ maskg,
                               const float* __restrict__ W_Q,
                               const float* __restrict__ W_O,
                               float* __restrict__ out)
{
    extern __shared__ char sm[];
    const uint32_t sb = smem_u32(sm);
    const int tid = threadIdx.x;
    const int wid = tid >> 5;
    const int lane = tid & 31;
    const int node0 = blockIdx.x * G_;

    float*  s_red   = (float*)(sm + OFF_RED);
    __half* s_k1    = (__half*)(sm + OFF_K1);
    float*  s_hv    = (float*)(sm + OFF_HV);
    float*  s_q     = (float*)(sm + OFF_Q);
    float*  s_logit = (float*)(sm + OFF_LOGIT);
    float*  s_att   = (float*)(sm + OFF_ATT);
    float*  s_mask  = (float*)(sm + OFF_MASK);
    float*  s_hupd  = (float*)(sm + OFF_HUPD);

    const float* asrc[4] = { h_KE + (size_t)node0 * 3840, h_KV + (size_t)node0 * 3840,
                             h_EV + (size_t)node0 * 7680, h_EV + (size_t)node0 * 7680 };
    const int    arst[4] = { 128, 128, 256, 256 };
    const int    acol[4] = { 0, 0, 0, 128 };

    // stage phase ph_'s A tile (raw f32, swizzled 8B granules) into buffer bufo
    auto stage = [&](int ph_, uint32_t bufo) {
        const float* src = asrc[ph_];
        const int rs = arst[ph_], co = acol[ph_];
        #pragma unroll
        for (int s = tid; s < 4096; s += NTHR) {
            int r = s >> 6, gg = s & 63;
            uint32_t dst = sb + bufo + (uint32_t)(r * 512 + ((gg ^ ((r & 3) << 2)) << 3));
            int rr = (r < MROWS) ? r : 0;
            const float* sp_ = src + (size_t)rr * rs + co + 2 * gg;
            uint32_t sz = (r < MROWS) ? 8u : 0u;
            CP_ASYNC8(dst, sp_, sz);
        }
        CP_COMMIT();
    };

    // ---- prologue: kick off ph0 staging, then Q projection under it ----
    stage(0, OFF_BUF0);

    if (tid < 64) ((float4*)s_hv)[tid] = ((const float4*)(h_V + (size_t)node0 * 128))[tid];
    if (tid < MROWS) s_mask[tid] = maskg[(size_t)node0 * K_ + tid];
    __syncthreads();

    {   // Q[g][j], 256 outputs
        int g = tid >> 7, j = tid & 127;
        const float4* wq = (const float4*)(W_Q + (size_t)j * 128);
        const float4* hv = (const float4*)(s_hv + g * 128);
        float acc0 = 0.f;
        #pragma unroll
        for (int d = 0; d < 32; d++) {
            float4 w = wq[d], x = hv[d];
            acc0 += w.x * x.x + w.y * x.y + w.z * x.z + w.w * x.w;
        }
        s_q[tid] = acc0;
    }

    // ---- warp tiling: 8 warps, each m32 x n32 ----
    const int wm = wid & 1;          // m-tile: rows wm*32 .. +31
    const int wn = wid >> 1;         // n32 block == head wn
    const int qrow = lane >> 2;      // 0..7
    const int pA   = lane & 3;
    const int dn   = pA * 2;
    const uint32_t swA = (uint32_t)((qrow & 3) << 2);
    const uint32_t arowb = (uint32_t)((wm * 32 + qrow) * 512);

    int rown[2][2], gof[2][2], kof[2][2];
    #pragma unroll
    for (int mt = 0; mt < 2; mt++)
        #pragma unroll
        for (int rh = 0; rh < 2; rh++) {
            int r = wm * 32 + mt * 16 + rh * 8 + qrow;
            rown[mt][rh] = r;
            gof[mt][rh] = (r < MROWS) ? (r / K_) : 0;
            kof[mt][rh] = (r < MROWS) ? (r % K_) : 0;
        }

    float acc[2][4][4];

    CP_WAIT0();
    __syncthreads();   // ph0 A tile visible

    for (int ph = 0; ph < 4; ph++) {
        // kick off next phase's staging into the other buffer
        if (ph < 3) stage(ph + 1, (uint32_t)(((ph + 1) & 1) ? OFF_BUF1 : OFF_BUF0));

        const uint32_t bufr = (uint32_t)((ph & 1) ? OFF_BUF1 : OFF_BUF0);

        if (ph != 3) {
            #pragma unroll
            for (int mt = 0; mt < 2; mt++)
                #pragma unroll
                for (int nt = 0; nt < 4; nt++)
                    #pragma unroll
                    for (int j = 0; j < 4; j++) acc[mt][nt][j] = 0.f;
        }

        // ---- k-loop: 8 k16 steps, single fp16 term ----
        #pragma unroll
        for (int ks = 0; ks < 8; ks++) {
            // B fragments (fp16, L2-hot, fragment-ordered)
            const uint4* bb = g_wfrag + ph * 2048 + ks * 256 + wn * 64 + lane;
            uint4 b0 = __ldg(bb);
            uint4 b1 = __ldg(bb + 32);

            // A fragments: f32 pairs from swizzled smem -> fp16x2
            uint32_t g0 = (uint32_t)((((uint32_t)(ks * 8 + pA)) ^ swA) << 3);
            uint32_t g1 = (uint32_t)((((uint32_t)(ks * 8 + 4 + pA)) ^ swA) << 3);
            uint32_t af[2][4];
            #pragma unroll
            for (int mt = 0; mt < 2; mt++) {
                const char* rb = sm + bufr + arowb + (uint32_t)(mt * 16 * 512);
                af[mt][0] = pack2h(*(const float2*)(rb + g0));
                af[mt][1] = pack2h(*(const float2*)(rb + 8 * 512 + g0));
                af[mt][2] = pack2h(*(const float2*)(rb + g1));
                af[mt][3] = pack2h(*(const float2*)(rb + 8 * 512 + g1));
            }
            #pragma unroll
            for (int mt = 0; mt < 2; mt++) {
                mma16816f(acc[mt][0], af[mt], b0.x, b0.y);
                mma16816f(acc[mt][1], af[mt], b0.z, b0.w);
                mma16816f(acc[mt][2], af[mt], b1.x, b1.y);
                mma16816f(acc[mt][3], af[mt], b1.z, b1.w);
            }
        }

        if (ph == 0) {
            // ---- store K1 as fp16 (rows & cols warp-private; same warp reads in ph1) ----
            #pragma unroll
            for (int mt = 0; mt < 2; mt++)
                #pragma unroll
                for (int nt = 0; nt < 4; nt++) {
                    int c = wn * 32 + nt * 8 + dn;
                    if (rown[mt][0] < MROWS)
                        *(half2*)&s_k1[rown[mt][0] * 132 + c] = __floats2half2_rn(acc[mt][nt][0], acc[mt][nt][1]);
                    if (rown[mt][1] < MROWS)
                        *(half2*)&s_k1[rown[mt][1] * 132 + c] = __floats2half2_rn(acc[mt][nt][2], acc[mt][nt][3]);
                }
        } else if (ph == 1) {
            // ---- trilinear logits for head wn over this warp's 32 cols ----
            float part[2][2];
            part[0][0] = part[0][1] = part[1][0] = part[1][1] = 0.f;
            #pragma unroll
            for (int mt = 0; mt < 2; mt++)
                #pragma unroll
                for (int nt = 0; nt < 4; nt++) {
                    int c = wn * 32 + nt * 8 + dn;
                    #pragma unroll
                    for (int rh = 0; rh < 2; rh++) {
                        int r = rown[mt][rh];
                        if (r < MROWS) {
                            float2 k1 = __half22float2(*(half2*)&s_k1[r * 132 + c]);
                            float2 q2 = *(float2*)&s_q[gof[mt][rh] * 128 + c];
                            part[mt][rh] += q2.x * k1.x * acc[mt][nt][2 * rh]
                                          + q2.y * k1.y * acc[mt][nt][2 * rh + 1];
                        }
                    }
                }
            #pragma unroll
            for (int mt = 0; mt < 2; mt++)
                #pragma unroll
                for (int rh = 0; rh < 2; rh++) {
                    float p = part[mt][rh];
                    p += __shfl_xor_sync(0xffffffffu, p, 1);
                    p += __shfl_xor_sync(0xffffffffu, p, 2);
                    if ((lane & 3) == 0 && rown[mt][rh] < MROWS)
                        s_logit[rown[mt][rh] * 4 + wn] = p * (1.0f / 32.0f);
                }
            __syncthreads();
            // ---- masked softmax per (g,h) ----
            if (tid < 8) {
                const int g = tid >> 2, h = tid & 3;
                const float NEG = -3.4028234663852886e38f;  // float32.min, matches reference
                float m = NEG;
                for (int k = 0; k < K_; k++) {
                    float msk = s_mask[g * K_ + k];
                    float l = (msk > 0.f) ? s_logit[(g * K_ + k) * 4 + h] : NEG;
                    m = fmaxf(m, l);
                }
                float ssum = 0.f;
                for (int k = 0; k < K_; k++) {
                    float msk = s_mask[g * K_ + k];
                    float l = (msk > 0.f) ? s_logit[(g * K_ + k) * 4 + h] : NEG;
                    float e = expf(l - m);
                    s_att[(g * 4 + h) * K_ + k] = e;
                    ssum += e;
                }
                float inv = 1.0f / ssum;
                for (int k = 0; k < K_; k++)
                    s_att[(g * 4 + h) * K_ + k] *= inv * s_mask[g * K_ + k];
            }
            __syncthreads();   // s_att visible to all
        }

        // next phase's tile must be resident before its k-loop
        CP_WAIT0();
        __syncthreads();
    }

    // ---- scale V acc by attend (head = wn), store to reduction buffer (aliases BUF0) ----
    {
        float aatt[2][2];
        #pragma unroll
        for (int mt = 0; mt < 2; mt++)
            #pragma unroll
            for (int rh = 0; rh < 2; rh++)
                aatt[mt][rh] = (rown[mt][rh] < MROWS)
                    ? s_att[(gof[mt][rh] * 4 + wn) * K_ + kof[mt][rh]] : 0.f;
        #pragma unroll
        for (int mt = 0; mt < 2; mt++)
            #pragma unroll
            for (int nt = 0; nt < 4; nt++) {
                int c = wn * 32 + nt * 8 + dn;
                if (rown[mt][0] < MROWS)
                    *(float2*)&s_red[rown[mt][0] * 132 + c] =
                        make_float2(aatt[mt][0] * acc[mt][nt][0], aatt[mt][0] * acc[mt][nt][1]);
                if (rown[mt][1] < MROWS)
                    *(float2*)&s_red[rown[mt][1] * 132 + c] =
                        make_float2(aatt[mt][1] * acc[mt][nt][2], aatt[mt][1] * acc[mt][nt][3]);
            }
    }
    __syncthreads();

    // ---- reduce over neighbors: h_upd[g][j] = sum_k red[g*30+k][j] ----
    {
        int g = tid >> 7, j = tid & 127;
        float acc2 = 0.f;
        #pragma unroll
        for (int k = 0; k < K_; k++)
            acc2 += s_red[(g * K_ + k) * 132 + j];
        s_hupd[tid] = acc2;
    }
    __syncthreads();

    // ---- output projection ----
    {
        int g = tid >> 7, i = tid & 127;
        const float4* wo = (const float4*)(W_O + (size_t)i * 128);
        const float4* hu = (const float4*)(s_hupd + g * 128);
        float acc2 = 0.f;
        #pragma unroll
        for (int c = 0; c < 32; c++) {
            float4 w = wo[c], x = hu[c];
            acc2 += w.x * x.x + w.y * x.y + w.z * x.z + w.w * x.w;
        }
        out[(size_t)(node0 + g) * 128 + i] = acc2;
    }
}

extern "C" void kernel_launch(void* const* d_in, const int* in_sizes, int n_in,
                              void* d_out, int out_size)
{
    const float* h_V  = (const float*)d_in[0];
    const float* h_EV = (const float*)d_in[1];
    const float* h_KV = (const float*)d_in[2];
    const float* h_KE = (const float*)d_in[3];
    const float* mask = (const float*)d_in[4];
    const float* W_Q  = (const float*)d_in[5];
    const float* W_K1 = (const float*)d_in[6];
    const float* W_K2 = (const float*)d_in[7];
    const float* W_V  = (const float*)d_in[8];
    const float* W_O  = (const float*)d_in[9];
    float* out = (float*)d_out;

    convert_weights_kernel<<<256, 256>>>(W_K1, W_K2, W_V);

    cudaFuncSetAttribute(neighbor_attn_hmma_kernel,
                         cudaFuncAttributeMaxDynamicSharedMemorySize, SMEM_BYTES);
    neighbor_attn_hmma_kernel<<<GRID, NTHR, SMEM_BYTES>>>(
        h_V, h_EV, h_KV, h_KE, mask, W_Q, W_O, out);
}

// round 13
// speedup vs baseline: 3.4698x; 1.0362x over previous
#include <cuda_runtime.h>
#include <cuda_bf16.h>
#include <cuda_fp16.h>
#include <cstdint>
#include <math.h>

// ---------------- problem constants ----------------
#define B_     4
#define N_     2000
#define K_     30
#define H_     128
#define NIN_   256
#define NODES  (B_ * N_)
#define G_     2              // nodes per CTA
#define MROWS  (G_ * K_)      // 60 valid rows of the 64-row M tile
#define GRID   (NODES / G_)   // 4000 CTAs
#define NTHR   256

// ---------------- smem layout (bytes) ----------------
// A staged as raw f32 [64 rows x 128 f32 = 512B rows], XOR-swizzled 16B chunks
#define OFF_BUF0  0          // 32KB
#define OFF_BUF1  32768      // 32KB
#define OFF_K1    65536      // K1 fp16: 60 x 132 half = 15840 (pad to 16000)
#define OFF_HV    81536      // 2x128 f32
#define OFF_Q     82560      // 2x128 f32
#define OFF_LOGIT 83584      // 60x4 f32
#define OFF_ATT   84608      // 8x30 f32
#define OFF_MASK  85632      // 60 f32
#define OFF_HUPD  85888      // 2x128 f32
#define SMEM_BYTES 86912
// V-reduction buffer (60 x 132 f32 = 31680) aliases BUF0
#define OFF_RED   0

// Weights pre-packed as fp16 in mma B-fragment order (n32 granularity):
// flat uint4 = ph*2048 + ks*256 + wn32*64 + qh*32 + lane
__device__ uint4 g_wfrag[8192];   // 128 KB

// ---------------- helpers ----------------
static __device__ __forceinline__ uint32_t smem_u32(const void* p) {
    uint32_t a;
    asm("{ .reg .u64 t; cvta.to.shared.u64 t, %1; cvt.u32.u64 %0, t; }" : "=r"(a) : "l"(p));
    return a;
}
static __device__ __forceinline__ void mma16816f(float* c, const uint32_t* a, uint32_t b0, uint32_t b1) {
    asm volatile("mma.sync.aligned.m16n8k16.row.col.f32.f16.f16.f32 "
                 "{%0,%1,%2,%3}, {%4,%5,%6,%7}, {%8,%9}, {%0,%1,%2,%3};"
                 : "+f"(c[0]), "+f"(c[1]), "+f"(c[2]), "+f"(c[3])
                 : "r"(a[0]), "r"(a[1]), "r"(a[2]), "r"(a[3]), "r"(b0), "r"(b1));
}
static __device__ __forceinline__ uint32_t pack2h(float2 v) {
    __half2 t = __floats2half2_rn(v.x, v.y);
    return *reinterpret_cast<uint32_t*>(&t);
}
#define CP_ASYNC16(dst, src, sz) \
    asm volatile("cp.async.cg.shared.global [%0], [%1], 16, %2;" :: "r"(dst), "l"(src), "r"(sz) : "memory")
#define CP_COMMIT()  asm volatile("cp.async.commit_group;" ::: "memory")
#define CP_WAIT0()   asm volatile("cp.async.wait_group 0;" ::: "memory")

// ---------------- weight pre-pack kernel (fp16, fragment order, n32 blocks) ----------------
__global__ void convert_weights_kernel(const float* __restrict__ Wk1,
                                       const float* __restrict__ Wk2,
                                       const float* __restrict__ Wv)
{
    int idx = blockIdx.x * blockDim.x + threadIdx.x;   // 4 * 16384
    int ph = idx >> 14;
    int e = idx & 16383;
    int n = e >> 7, k = e & 127;
    float v;
    if (ph == 0)      v = Wk1[n * 128 + k];
    else if (ph == 1) v = Wk2[n * 128 + k];
    else if (ph == 2) v = Wv[n * 256 + k];
    else              v = Wv[n * 256 + 128 + k];
    __half h = __float2half(v);

    int ks = k >> 4, kk = k & 15;
    int wn = n >> 5, nl = n & 31;
    int nt = nl >> 3, nr = nl & 7;
    int t  = nr * 4 + ((kk & 7) >> 1);        // lane
    int rg = (nt & 1) * 2 + (kk >= 8);        // word in uint4
    int qh = nt >> 1;
    int ee = kk & 1;

    int flat = ph * 2048 + ks * 256 + wn * 64 + qh * 32 + t;
    *reinterpret_cast<__half*>((char*)g_wfrag + (size_t)flat * 16 + rg * 4 + ee * 2) = h;
}

// ---------------- main fused kernel ----------------
__global__ __launch_bounds__(NTHR, 2)
void neighbor_attn_hmma_kernel(const float* __restrict__ h_V,
                               const float* __restrict__ h_EV,
                               const float* __restrict__ h_KV,
                               const float* __restrict__ h_KE,
                               const float* __restrict__ maskg,
                               const float* __restrict__ W_Q,
                               const float* __restrict__ W_O,
                               float* __restrict__ out)
{
    extern __shared__ char sm[];
    const uint32_t sb = smem_u32(sm);
    const int tid = threadIdx.x;
    const int wid = tid >> 5;
    const int lane = tid & 31;
    const int node0 = blockIdx.x * G_;

    float*  s_red   = (float*)(sm + OFF_RED);
    __half* s_k1    = (__half*)(sm + OFF_K1);
    float*  s_hv    = (float*)(sm + OFF_HV);
    float*  s_q     = (float*)(sm + OFF_Q);
    float*  s_logit = (float*)(sm + OFF_LOGIT);
    float*  s_att   = (float*)(sm + OFF_ATT);
    float*  s_mask  = (float*)(sm + OFF_MASK);
    float*  s_hupd  = (float*)(sm + OFF_HUPD);

    const float* asrc[4] = { h_KE + (size_t)node0 * 3840, h_KV + (size_t)node0 * 3840,
                             h_EV + (size_t)node0 * 7680, h_EV + (size_t)node0 * 7680 };
    const int    arst[4] = { 128, 128, 256, 256 };
    const int    acol[4] = { 0, 0, 0, 128 };

    // stage phase ph_'s A tile (raw f32, swizzled 16B chunks) into buffer bufo
    // (16B-chunk swizzle c^((r&3)<<1) is byte-identical to the 8B-granule
    //  swizzle g^((r&3)<<2) used by the readers)
    auto stage = [&](int ph_, uint32_t bufo) {
        const float* src = asrc[ph_];
        const int rs = arst[ph_], co = acol[ph_];
        #pragma unroll
        for (int s = tid; s < 2048; s += NTHR) {
            int r = s >> 5, c = s & 31;
            uint32_t dst = sb + bufo + (uint32_t)(r * 512 + ((c ^ ((r & 3) << 1)) << 4));
            int rr = (r < MROWS) ? r : 0;
            const float* sp_ = src + (size_t)rr * rs + co + 4 * c;
            uint32_t sz = (r < MROWS) ? 16u : 0u;
            CP_ASYNC16(dst, sp_, sz);
        }
        CP_COMMIT();
    };

    // ---- prologue: kick off ph0 staging, then Q projection under it ----
    stage(0, OFF_BUF0);

    if (tid < 64) ((float4*)s_hv)[tid] = ((const float4*)(h_V + (size_t)node0 * 128))[tid];
    if (tid < MROWS) s_mask[tid] = maskg[(size_t)node0 * K_ + tid];
    __syncthreads();

    {   // Q[g][j], 256 outputs
        int g = tid >> 7, j = tid & 127;
        const float4* wq = (const float4*)(W_Q + (size_t)j * 128);
        const float4* hv = (const float4*)(s_hv + g * 128);
        float acc0 = 0.f;
        #pragma unroll
        for (int d = 0; d < 32; d++) {
            float4 w = wq[d], x = hv[d];
            acc0 += w.x * x.x + w.y * x.y + w.z * x.z + w.w * x.w;
        }
        s_q[tid] = acc0;
    }

    // ---- warp tiling: 8 warps, each m16 x n64 ----
    const int wm = wid & 3;          // m-group: rows wm*16 .. +15
    const int wn = wid >> 2;         // n-half: cols wn*64 .. +63 (heads wn*2, wn*2+1)
    const int qrow = lane >> 2;      // 0..7
    const int pA   = lane & 3;
    const int dn   = pA * 2;
    const uint32_t swA = (uint32_t)((qrow & 3) << 2);
    const uint32_t arowb = (uint32_t)((wm * 16 + qrow) * 512);

    int rown[2], gof[2], kof[2];
    #pragma unroll
    for (int rh = 0; rh < 2; rh++) {
        int r = wm * 16 + rh * 8 + qrow;
        rown[rh] = r;
        gof[rh] = (r < MROWS) ? (r / K_) : 0;
        kof[rh] = (r < MROWS) ? (r % K_) : 0;
    }

    float acc[8][4];

    CP_WAIT0();
    __syncthreads();   // ph0 A tile visible

    for (int ph = 0; ph < 4; ph++) {
        // kick off next phase's staging into the other buffer
        if (ph < 3) stage(ph + 1, (uint32_t)(((ph + 1) & 1) ? OFF_BUF1 : OFF_BUF0));

        const uint32_t bufr = (uint32_t)((ph & 1) ? OFF_BUF1 : OFF_BUF0);

        if (ph != 3) {
            #pragma unroll
            for (int nt = 0; nt < 8; nt++)
                #pragma unroll
                for (int j = 0; j < 4; j++) acc[nt][j] = 0.f;
        }

        // ---- k-loop: 8 k16 steps, single fp16 term ----
        #pragma unroll
        for (int ks = 0; ks < 8; ks++) {
            // B fragments (fp16, L2-hot, fragment-ordered): 2 n32 blocks
            const uint4* bb = g_wfrag + ph * 2048 + ks * 256 + (wn * 2) * 64 + lane;
            uint4 b00 = __ldg(bb);
            uint4 b01 = __ldg(bb + 32);
            uint4 b10 = __ldg(bb + 64);
            uint4 b11 = __ldg(bb + 96);

            // A fragments: f32 pairs from swizzled smem -> fp16x2 (m16k16)
            uint32_t g0 = (uint32_t)((((uint32_t)(ks * 8 + pA)) ^ swA) << 3);
            uint32_t g1 = (uint32_t)((((uint32_t)(ks * 8 + 4 + pA)) ^ swA) << 3);
            const char* rb = sm + bufr + arowb;
            uint32_t af[4];
            af[0] = pack2h(*(const float2*)(rb + g0));
            af[1] = pack2h(*(const float2*)(rb + 8 * 512 + g0));
            af[2] = pack2h(*(const float2*)(rb + g1));
            af[3] = pack2h(*(const float2*)(rb + 8 * 512 + g1));

            mma16816f(acc[0], af, b00.x, b00.y);
            mma16816f(acc[1], af, b00.z, b00.w);
            mma16816f(acc[2], af, b01.x, b01.y);
            mma16816f(acc[3], af, b01.z, b01.w);
            mma16816f(acc[4], af, b10.x, b10.y);
            mma16816f(acc[5], af, b10.z, b10.w);
            mma16816f(acc[6], af, b11.x, b11.y);
            mma16816f(acc[7], af, b11.z, b11.w);
        }

        if (ph == 0) {
            // ---- store K1 as fp16 (rows & cols warp-private; same warp reads in ph1) ----
            #pragma unroll
            for (int nt = 0; nt < 8; nt++) {
                int c = wn * 64 + nt * 8 + dn;
                if (rown[0] < MROWS)
                    *(half2*)&s_k1[rown[0] * 132 + c] = __floats2half2_rn(acc[nt][0], acc[nt][1]);
                if (rown[1] < MROWS)
                    *(half2*)&s_k1[rown[1] * 132 + c] = __floats2half2_rn(acc[nt][2], acc[nt][3]);
            }
        } else if (ph == 1) {
            // ---- trilinear logits for heads wn*2+hh over this warp's 64 cols ----
            float part[2][2];   // [rh][hh]
            part[0][0] = part[0][1] = part[1][0] = part[1][1] = 0.f;
            #pragma unroll
            for (int nt = 0; nt < 8; nt++) {
                int c = wn * 64 + nt * 8 + dn;
                int hh = nt >> 2;
                #pragma unroll
                for (int rh = 0; rh < 2; rh++) {
                    int r = rown[rh];
                    if (r < MROWS) {
                        float2 k1 = __half22float2(*(half2*)&s_k1[r * 132 + c]);
                        float2 q2 = *(float2*)&s_q[gof[rh] * 128 + c];
                        part[rh][hh] += q2.x * k1.x * acc[nt][2 * rh]
                                      + q2.y * k1.y * acc[nt][2 * rh + 1];
                    }
                }
            }
            #pragma unroll
            for (int rh = 0; rh < 2; rh++)
                #pragma unroll
                for (int hh = 0; hh < 2; hh++) {
                    float p = part[rh][hh];
                    p += __shfl_xor_sync(0xffffffffu, p, 1);
                    p += __shfl_xor_sync(0xffffffffu, p, 2);
                    if ((lane & 3) == 0 && rown[rh] < MROWS)
                        s_logit[rown[rh] * 4 + wn * 2 + hh] = p * (1.0f / 32.0f);
                }
            __syncthreads();
            // ---- masked softmax per (g,h) ----
            if (tid < 8) {
                const int g = tid >> 2, h = tid & 3;
                const float NEG = -3.4028234663852886e38f;  // float32.min, matches reference
                float m = NEG;
                for (int k = 0; k < K_; k++) {
                    float msk = s_mask[g * K_ + k];
                    float l = (msk > 0.f) ? s_logit[(g * K_ + k) * 4 + h] : NEG;
                    m = fmaxf(m, l);
                }
                float ssum = 0.f;
                for (int k = 0; k < K_; k++) {
                    float msk = s_mask[g * K_ + k];
                    float l = (msk > 0.f) ? s_logit[(g * K_ + k) * 4 + h] : NEG;
                    float e = expf(l - m);
                    s_att[(g * 4 + h) * K_ + k] = e;
                    ssum += e;
                }
                float inv = 1.0f / ssum;
                for (int k = 0; k < K_; k++)
                    s_att[(g * 4 + h) * K_ + k] *= inv * s_mask[g * K_ + k];
            }
            __syncthreads();   // s_att visible to all
        }

        // next phase's tile must be resident before its k-loop
        CP_WAIT0();
        __syncthreads();
    }

    // ---- scale V acc by attend (heads wn*2+hh), store to reduction buffer (aliases BUF0) ----
    {
        float aatt[2][2];   // [rh][hh]
        #pragma unroll
        for (int rh = 0; rh < 2; rh++)
            #pragma unroll
            for (int hh = 0; hh < 2; hh++)
                aatt[rh][hh] = (rown[rh] < MROWS)
                    ? s_att[(gof[rh] * 4 + wn * 2 + hh) * K_ + kof[rh]] : 0.f;
        #pragma unroll
        for (int nt = 0; nt < 8; nt++) {
            int c = wn * 64 + nt * 8 + dn;
            int hh = nt >> 2;
            if (rown[0] < MROWS)
                *(float2*)&s_red[rown[0] * 132 + c] =
                    make_float2(aatt[0][hh] * acc[nt][0], aatt[0][hh] * acc[nt][1]);
            if (rown[1] < MROWS)
                *(float2*)&s_red[rown[1] * 132 + c] =
                    make_float2(aatt[1][hh] * acc[nt][2], aatt[1][hh] * acc[nt][3]);
        }
    }
    __syncthreads();

    // ---- reduce over neighbors: h_upd[g][j] = sum_k red[g*30+k][j] ----
    {
        int g = tid >> 7, j = tid & 127;
        float acc2 = 0.f;
        #pragma unroll
        for (int k = 0; k < K_; k++)
            acc2 += s_red[(g * K_ + k) * 132 + j];
        s_hupd[tid] = acc2;
    }
    __syncthreads();

    // ---- output projection ----
    {
        int g = tid >> 7, i = tid & 127;
        const float4* wo = (const float4*)(W_O + (size_t)i * 128);
        const float4* hu = (const float4*)(s_hupd + g * 128);
        float acc2 = 0.f;
        #pragma unroll
        for (int c = 0; c < 32; c++) {
            float4 w = wo[c], x = hu[c];
            acc2 += w.x * x.x + w.y * x.y + w.z * x.z + w.w * x.w;
        }
        out[(size_t)(node0 + g) * 128 + i] = acc2;
    }
}

extern "C" void kernel_launch(void* const* d_in, const int* in_sizes, int n_in,
                              void* d_out, int out_size)
{
    const float* h_V  = (const float*)d_in[0];
    const float* h_EV = (const float*)d_in[1];
    const float* h_KV = (const float*)d_in[2];
    const float* h_KE = (const float*)d_in[3];
    const float* mask = (const float*)d_in[4];
    const float* W_Q  = (const float*)d_in[5];
    const float* W_K1 = (const float*)d_in[6];
    const float* W_K2 = (const float*)d_in[7];
    const float* W_V  = (const float*)d_in[8];
    const float* W_O  = (const float*)d_in[9];
    float* out = (float*)d_out;

    convert_weights_kernel<<<256, 256>>>(W_K1, W_K2, W_V);

    cudaFuncSetAttribute(neighbor_attn_hmma_kernel,
                         cudaFuncAttributeMaxDynamicSharedMemorySize, SMEM_BYTES);
    neighbor_attn_hmma_kernel<<<GRID, NTHR, SMEM_BYTES>>>(
        h_V, h_EV, h_KV, h_KE, mask, W_Q, W_O, out);
}

// round 17
// speedup vs baseline: 4.3058x; 1.2410x over previous
#include <cuda_runtime.h>
#include <cuda_bf16.h>
#include <cuda_fp16.h>
#include <cstdint>
#include <math.h>

// ---------------- problem constants ----------------
#define B_     4
#define N_     2000
#define K_     30
#define H_     128
#define NIN_   256
#define NODES  (B_ * N_)
#define G_     2              // nodes per CTA
#define MROWS  (G_ * K_)      // 60 valid rows of the 64-row M tile
#define GRID   (NODES / G_)   // 4000 CTAs
#define NTHR   256

// ---------------- smem layout (bytes) ----------------
// A staged as raw f32 [64 rows x 128 f32 = 512B rows], XOR-swizzled 16B chunks
#define OFF_BUF0  0          // 32KB  (later: V-reduction partial kw=0)
#define OFF_BUF1  32768      // 32KB  (later: V-reduction partial kw=1)
#define K1_BYTES  16000
#define OFF_K1    65536      // two K1 fp16 partial buffers (60 x 132 half each)
#define OFF_HV    97536      // 2x128 f32
#define OFF_Q     98560      // 2x128 f32
#define OFF_LOGIT 99584      // 60 x 4 x 2 f32 partial logits (1920 -> 2048)
#define OFF_ATT   101632     // 8x30 f32
#define OFF_MASK  102656     // 60 f32
#define OFF_HUPD  102912     // 2x128 f32
#define SMEM_BYTES 103936

// Weights pre-packed as fp16 in mma B-fragment order (n32 granularity):
// flat uint4 = ph*2048 + ks*256 + wn32*64 + qh*32 + lane
__device__ uint4 g_wfrag[8192];   // 128 KB

// ---------------- helpers ----------------
static __device__ __forceinline__ uint32_t smem_u32(const void* p) {
    uint32_t a;
    asm("{ .reg .u64 t; cvta.to.shared.u64 t, %1; cvt.u32.u64 %0, t; }" : "=r"(a) : "l"(p));
    return a;
}
static __device__ __forceinline__ void mma16816f(float* c, const uint32_t* a, uint32_t b0, uint32_t b1) {
    asm volatile("mma.sync.aligned.m16n8k16.row.col.f32.f16.f16.f32 "
                 "{%0,%1,%2,%3}, {%4,%5,%6,%7}, {%8,%9}, {%0,%1,%2,%3};"
                 : "+f"(c[0]), "+f"(c[1]), "+f"(c[2]), "+f"(c[3])
                 : "r"(a[0]), "r"(a[1]), "r"(a[2]), "r"(a[3]), "r"(b0), "r"(b1));
}
static __device__ __forceinline__ uint32_t pack2h(float2 v) {
    __half2 t = __floats2half2_rn(v.x, v.y);
    return *reinterpret_cast<uint32_t*>(&t);
}
#define CP_ASYNC16(dst, src, sz) \
    asm volatile("cp.async.cg.shared.global [%0], [%1], 16, %2;" :: "r"(dst), "l"(src), "r"(sz) : "memory")
#define CP_COMMIT()  asm volatile("cp.async.commit_group;" ::: "memory")
#define CP_WAIT0()   asm volatile("cp.async.wait_group 0;" ::: "memory")

// ---------------- weight pre-pack kernel (fp16, fragment order, n32 blocks) ----------------
__global__ void convert_weights_kernel(const float* __restrict__ Wk1,
                                       const float* __restrict__ Wk2,
                                       const float* __restrict__ Wv)
{
    int idx = blockIdx.x * blockDim.x + threadIdx.x;   // 4 * 16384
    int ph = idx >> 14;
    int e = idx & 16383;
    int n = e >> 7, k = e & 127;
    float v;
    if (ph == 0)      v = Wk1[n * 128 + k];
    else if (ph == 1) v = Wk2[n * 128 + k];
    else if (ph == 2) v = Wv[n * 256 + k];
    else              v = Wv[n * 256 + 128 + k];
    __half h = __float2half(v);

    int ks = k >> 4, kk = k & 15;
    int wn = n >> 5, nl = n & 31;
    int nt = nl >> 3, nr = nl & 7;
    int t  = nr * 4 + ((kk & 7) >> 1);        // lane
    int rg = (nt & 1) * 2 + (kk >= 8);        // word in uint4
    int qh = nt >> 1;
    int ee = kk & 1;

    int flat = ph * 2048 + ks * 256 + wn * 64 + qh * 32 + t;
    *reinterpret_cast<__half*>((char*)g_wfrag + (size_t)flat * 16 + rg * 4 + ee * 2) = h;
}

// ---------------- main fused kernel ----------------
__global__ __launch_bounds__(NTHR, 2)
void neighbor_attn_hmma_kernel(const float* __restrict__ h_V,
                               const float* __restrict__ h_EV,
                               const float* __restrict__ h_KV,
                               const float* __restrict__ h_KE,
                               const float* __restrict__ maskg,
                               const float* __restrict__ W_Q,
                               const float* __restrict__ W_O,
                               float* __restrict__ out)
{
    extern __shared__ char sm[];
    const uint32_t sb = smem_u32(sm);
    const int tid = threadIdx.x;
    const int wid = tid >> 5;
    const int lane = tid & 31;
    const int node0 = blockIdx.x * G_;

    float*  s_red0  = (float*)(sm + OFF_BUF0);
    float*  s_red1  = (float*)(sm + OFF_BUF1);
    __half* s_k1p0  = (__half*)(sm + OFF_K1);
    __half* s_k1p1  = (__half*)(sm + OFF_K1 + K1_BYTES);
    float*  s_hv    = (float*)(sm + OFF_HV);
    float*  s_q     = (float*)(sm + OFF_Q);
    float*  s_logit = (float*)(sm + OFF_LOGIT);
    float*  s_att   = (float*)(sm + OFF_ATT);
    float*  s_mask  = (float*)(sm + OFF_MASK);
    float*  s_hupd  = (float*)(sm + OFF_HUPD);

    const float* asrc[4] = { h_KE + (size_t)node0 * 3840, h_KV + (size_t)node0 * 3840,
                             h_EV + (size_t)node0 * 7680, h_EV + (size_t)node0 * 7680 };
    const int    arst[4] = { 128, 128, 256, 256 };
    const int    acol[4] = { 0, 0, 0, 128 };

    // stage phase ph_'s A tile (raw f32, swizzled 16B chunks) into buffer bufo
    auto stage = [&](int ph_, uint32_t bufo) {
        const float* src = asrc[ph_];
        const int rs = arst[ph_], co = acol[ph_];
        #pragma unroll
        for (int s = tid; s < 2048; s += NTHR) {
            int r = s >> 5, c = s & 31;
            uint32_t dst = sb + bufo + (uint32_t)(r * 512 + ((c ^ ((r & 3) << 1)) << 4));
            int rr = (r < MROWS) ? r : 0;
            const float* sp_ = src + (size_t)rr * rs + co + 4 * c;
            uint32_t sz = (r < MROWS) ? 16u : 0u;
            CP_ASYNC16(dst, sp_, sz);
        }
        CP_COMMIT();
    };

    // ---- prologue: kick off ph0 staging, then Q projection under it ----
    stage(0, OFF_BUF0);

    if (tid < 64) ((float4*)s_hv)[tid] = ((const float4*)(h_V + (size_t)node0 * 128))[tid];
    if (tid < MROWS) s_mask[tid] = maskg[(size_t)node0 * K_ + tid];
    __syncthreads();

    // Q[g][j]: each of 128 threads reads one W_Q row once, computes both g
    if (tid < 128) {
        const float4* wq = (const float4*)(W_Q + (size_t)tid * 128);
        const float4* h0 = (const float4*)(s_hv);
        const float4* h1 = (const float4*)(s_hv + 128);
        float a0 = 0.f, a1 = 0.f;
        #pragma unroll
        for (int d = 0; d < 32; d++) {
            float4 w = wq[d], x0 = h0[d], x1 = h1[d];
            a0 += w.x * x0.x + w.y * x0.y + w.z * x0.z + w.w * x0.w;
            a1 += w.x * x1.x + w.y * x1.y + w.z * x1.z + w.w * x1.w;
        }
        s_q[tid] = a0;
        s_q[128 + tid] = a1;
    }

    // ---- warp tiling: 8 warps = (kw, wm, wn); each m32 x n64 x k64 ----
    const int kw = wid & 1;          // k-half
    const int wm = (wid >> 1) & 1;   // m-half: rows wm*32 .. +31
    const int wn = wid >> 2;         // n-half: cols wn*64 .. +63 (heads wn*2, wn*2+1)
    const int qrow = lane >> 2;      // 0..7
    const int pA   = lane & 3;
    const int dn   = pA * 2;
    const uint32_t swA = (uint32_t)((qrow & 3) << 2);
    const uint32_t arowb = (uint32_t)((wm * 32 + qrow) * 512);

    int rown[2][2], gof[2][2], kof[2][2];   // [mt][rh]
    #pragma unroll
    for (int mt = 0; mt < 2; mt++)
        #pragma unroll
        for (int rh = 0; rh < 2; rh++) {
            int r = wm * 32 + mt * 16 + rh * 8 + qrow;
            rown[mt][rh] = r;
            gof[mt][rh] = (r < MROWS) ? (r / K_) : 0;
            kof[mt][rh] = (r < MROWS) ? (r % K_) : 0;
        }

    __half* k1own = kw ? s_k1p1 : s_k1p0;

    float acc[2][8][4];

    CP_WAIT0();
    __syncthreads();   // ph0 A tile visible

    for (int ph = 0; ph < 4; ph++) {
        if (ph < 3) stage(ph + 1, (uint32_t)(((ph + 1) & 1) ? OFF_BUF1 : OFF_BUF0));

        const uint32_t bufr = (uint32_t)((ph & 1) ? OFF_BUF1 : OFF_BUF0);

        if (ph != 3) {
            #pragma unroll
            for (int mt = 0; mt < 2; mt++)
                #pragma unroll
                for (int nt = 0; nt < 8; nt++)
                    #pragma unroll
                    for (int j = 0; j < 4; j++) acc[mt][nt][j] = 0.f;
        }

        // ---- k-loop: this warp's 4 k16 steps (k-half kw) ----
        #pragma unroll
        for (int ksl = 0; ksl < 4; ksl++) {
            int ks = kw * 4 + ksl;
            const uint4* bb = g_wfrag + ph * 2048 + ks * 256 + (wn * 2) * 64 + lane;
            uint4 b00 = __ldg(bb);
            uint4 b01 = __ldg(bb + 32);
            uint4 b10 = __ldg(bb + 64);
            uint4 b11 = __ldg(bb + 96);

            uint32_t g0 = (uint32_t)((((uint32_t)(ks * 8 + pA)) ^ swA) << 3);
            uint32_t g1 = (uint32_t)((((uint32_t)(ks * 8 + 4 + pA)) ^ swA) << 3);
            #pragma unroll
            for (int mt = 0; mt < 2; mt++) {
                const char* rb = sm + bufr + arowb + (uint32_t)(mt * 16 * 512);
                uint32_t af[4];
                af[0] = pack2h(*(const float2*)(rb + g0));
                af[1] = pack2h(*(const float2*)(rb + 8 * 512 + g0));
                af[2] = pack2h(*(const float2*)(rb + g1));
                af[3] = pack2h(*(const float2*)(rb + 8 * 512 + g1));

                mma16816f(acc[mt][0], af, b00.x, b00.y);
                mma16816f(acc[mt][1], af, b00.z, b00.w);
                mma16816f(acc[mt][2], af, b01.x, b01.y);
                mma16816f(acc[mt][3], af, b01.z, b01.w);
                mma16816f(acc[mt][4], af, b10.x, b10.y);
                mma16816f(acc[mt][5], af, b10.z, b10.w);
                mma16816f(acc[mt][6], af, b11.x, b11.y);
                mma16816f(acc[mt][7], af, b11.z, b11.w);
            }
        }

        if (ph == 0) {
            // ---- store K1 k-partial as fp16 into this kw's buffer ----
            #pragma unroll
            for (int mt = 0; mt < 2; mt++)
                #pragma unroll
                for (int nt = 0; nt < 8; nt++) {
                    int c = wn * 64 + nt * 8 + dn;
                    if (rown[mt][0] < MROWS)
                        *(half2*)&k1own[rown[mt][0] * 132 + c] = __floats2half2_rn(acc[mt][nt][0], acc[mt][nt][1]);
                    if (rown[mt][1] < MROWS)
                        *(half2*)&k1own[rown[mt][1] * 132 + c] = __floats2half2_rn(acc[mt][nt][2], acc[mt][nt][3]);
                }
        } else if (ph == 1) {
            // ---- partial trilinear logits: q * (k1p0+k1p1) * k2_partial ----
            float part[2][2][2];   // [mt][rh][hh]
            #pragma unroll
            for (int mt = 0; mt < 2; mt++)
                part[mt][0][0] = part[mt][0][1] = part[mt][1][0] = part[mt][1][1] = 0.f;
            #pragma unroll
            for (int mt = 0; mt < 2; mt++)
                #pragma unroll
                for (int nt = 0; nt < 8; nt++) {
                    int c = wn * 64 + nt * 8 + dn;
                    int hh = nt >> 2;
                    #pragma unroll
                    for (int rh = 0; rh < 2; rh++) {
                        int r = rown[mt][rh];
                        if (r < MROWS) {
                            float2 ka = __half22float2(*(half2*)&s_k1p0[r * 132 + c]);
                            float2 kb = __half22float2(*(half2*)&s_k1p1[r * 132 + c]);
                            float2 q2 = *(float2*)&s_q[gof[mt][rh] * 128 + c];
                            part[mt][rh][hh] += q2.x * (ka.x + kb.x) * acc[mt][nt][2 * rh]
                                              + q2.y * (ka.y + kb.y) * acc[mt][nt][2 * rh + 1];
                        }
                    }
                }
            #pragma unroll
            for (int mt = 0; mt < 2; mt++)
                #pragma unroll
                for (int rh = 0; rh < 2; rh++)
                    #pragma unroll
                    for (int hh = 0; hh < 2; hh++) {
                        float p = part[mt][rh][hh];
                        p += __shfl_xor_sync(0xffffffffu, p, 1);
                        p += __shfl_xor_sync(0xffffffffu, p, 2);
                        if ((lane & 3) == 0 && rown[mt][rh] < MROWS)
                            s_logit[rown[mt][rh] * 8 + (wn * 2 + hh) * 2 + kw] = p * (1.0f / 32.0f);
                    }
            __syncthreads();
            // ---- masked softmax per (g,h): sum the two k-partial logit slots ----
            if (tid < 8) {
                const int g = tid >> 2, h = tid & 3;
                const float NEG = -3.4028234663852886e38f;  // float32.min, matches reference
                float m = NEG;
                for (int k = 0; k < K_; k++) {
                    int r = g * K_ + k;
                    float msk = s_mask[r];
                    float lg = s_logit[r * 8 + h * 2] + s_logit[r * 8 + h * 2 + 1];
                    float l = (msk > 0.f) ? lg : NEG;
                    m = fmaxf(m, l);
                }
                float ssum = 0.f;
                for (int k = 0; k < K_; k++) {
                    int r = g * K_ + k;
                    float msk = s_mask[r];
                    float lg = s_logit[r * 8 + h * 2] + s_logit[r * 8 + h * 2 + 1];
                    float l = (msk > 0.f) ? lg : NEG;
                    float e = expf(l - m);
                    s_att[(g * 4 + h) * K_ + k] = e;
                    ssum += e;
                }
                float inv = 1.0f / ssum;
                for (int k = 0; k < K_; k++)
                    s_att[(g * 4 + h) * K_ + k] *= inv * s_mask[g * K_ + k];
            }
            __syncthreads();   // s_att visible to all
        }

        // next phase's tile must be resident before its k-loop
        CP_WAIT0();
        __syncthreads();
    }

    // ---- scale V k-partials by attend, write to this kw's reduction buffer ----
    {
        float* s_redp = kw ? s_red1 : s_red0;
        float aatt[2][2][2];   // [mt][rh][hh]
        #pragma unroll
        for (int mt = 0; mt < 2; mt++)
            #pragma unroll
            for (int rh = 0; rh < 2; rh++)
                #pragma unroll
                for (int hh = 0; hh < 2; hh++)
                    aatt[mt][rh][hh] = (rown[mt][rh] < MROWS)
                        ? s_att[(gof[mt][rh] * 4 + wn * 2 + hh) * K_ + kof[mt][rh]] : 0.f;
        #pragma unroll
        for (int mt = 0; mt < 2; mt++)
            #pragma unroll
            for (int nt = 0; nt < 8; nt++) {
                int c = wn * 64 + nt * 8 + dn;
                int hh = nt >> 2;
                if (rown[mt][0] < MROWS)
                    *(float2*)&s_redp[rown[mt][0] * 132 + c] =
                        make_float2(aatt[mt][0][hh] * acc[mt][nt][0], aatt[mt][0][hh] * acc[mt][nt][1]);
                if (rown[mt][1] < MROWS)
                    *(float2*)&s_redp[rown[mt][1] * 132 + c] =
                        make_float2(aatt[mt][1][hh] * acc[mt][nt][2], aatt[mt][1][hh] * acc[mt][nt][3]);
            }
    }
    __syncthreads();

    // ---- reduce over neighbors + k-partials: h_upd[g][j] ----
    {
        int g = tid >> 7, j = tid & 127;
        float acc2 = 0.f;
        #pragma unroll
        for (int k = 0; k < K_; k++) {
            int r = (g * K_ + k) * 132 + j;
            acc2 += s_red0[r] + s_red1[r];
        }
        s_hupd[tid] = acc2;
    }
    __syncthreads();

    // ---- output projection: 128 threads, each W_O row read once, both g ----
    if (tid < 128) {
        const float4* wo = (const float4*)(W_O + (size_t)tid * 128);
        const float4* h0 = (const float4*)(s_hupd);
        const float4* h1 = (const float4*)(s_hupd + 128);
        float a0 = 0.f, a1 = 0.f;
        #pragma unroll
        for (int c = 0; c < 32; c++) {
            float4 w = wo[c], x0 = h0[c], x1 = h1[c];
            a0 += w.x * x0.x + w.y * x0.y + w.z * x0.z + w.w * x0.w;
            a1 += w.x * x1.x + w.y * x1.y + w.z * x1.z + w.w * x1.w;
        }
        out[(size_t)node0 * 128 + tid] = a0;
        out[(size_t)(node0 + 1) * 128 + tid] = a1;
    }
}

extern "C" void kernel_launch(void* const* d_in, const int* in_sizes, int n_in,
                              void* d_out, int out_size)
{
    const float* h_V  = (const float*)d_in[0];
    const float* h_EV = (const float*)d_in[1];
    const float* h_KV = (const float*)d_in[2];
    const float* h_KE = (const float*)d_in[3];
    const float* mask = (const float*)d_in[4];
    const float* W_Q  = (const float*)d_in[5];
    const float* W_K1 = (const float*)d_in[6];
    const float* W_K2 = (const float*)d_in[7];
    const float* W_V  = (const float*)d_in[8];
    const float* W_O  = (const float*)d_in[9];
    float* out = (float*)d_out;

    convert_weights_kernel<<<256, 256>>>(W_K1, W_K2, W_V);

    cudaFuncSetAttribute(neighbor_attn_hmma_kernel,
                         cudaFuncAttributeMaxDynamicSharedMemorySize, SMEM_BYTES);
    neighbor_attn_hmma_kernel<<<GRID, NTHR, SMEM_BYTES>>>(
        h_V, h_EV, h_KV, h_KE, mask, W_Q, W_O, out);
}